// round 10
// baseline (speedup 1.0000x reference)
#include <cuda_runtime.h>
#include <cuda_bf16.h>
#include <mma.h>
#include <cstdint>

using namespace nvcuda;

#define BATCH 32768
#define DIN   768
#define DHID  2048
#define TOPK  32

// -------- scratch (no cudaMalloc allowed) --------
__device__ __align__(16) float g_Wt[(size_t)DHID * DIN];   // W_dec^T [2048][768]
__device__ int   g_tidx[(size_t)BATCH * TOPK];
__device__ float g_tval[(size_t)BATCH * TOPK];
__device__ __align__(16) __nv_bfloat16 g_Ah[(size_t)BATCH * DIN];
__device__ __align__(16) __nv_bfloat16 g_Al[(size_t)BATCH * DIN];
__device__ __align__(16) __nv_bfloat16 g_Bh[(size_t)DHID * DIN];
__device__ __align__(16) __nv_bfloat16 g_Bl[(size_t)DHID * DIN];

// ============================================================
// f32 -> (hi, lo) bf16 split
// ============================================================
__global__ __launch_bounds__(256)
void split_kernel(const float* __restrict__ src,
                  __nv_bfloat16* __restrict__ hi,
                  __nv_bfloat16* __restrict__ lo)
{
    int i = blockIdx.x * 256 + threadIdx.x;
    float2 v = ((const float2*)src)[i];
    __nv_bfloat16 h0 = __float2bfloat16(v.x);
    __nv_bfloat16 h1 = __float2bfloat16(v.y);
    __nv_bfloat16 l0 = __float2bfloat16(v.x - __bfloat162float(h0));
    __nv_bfloat16 l1 = __float2bfloat16(v.y - __bfloat162float(h1));
    ((__nv_bfloat162*)hi)[i] = __halves2bfloat162(h0, h1);
    ((__nv_bfloat162*)lo)[i] = __halves2bfloat162(l0, l1);
}

// ============================================================
// W_dec [768][2048] -> g_Wt [2048][768]
// ============================================================
__global__ void transpose_kernel(const float* __restrict__ W)
{
    __shared__ float tile[32][33];
    int bx = blockIdx.x * 32, by = blockIdx.y * 32;
    int tx = threadIdx.x, ty = threadIdx.y;
#pragma unroll
    for (int i = 0; i < 32; i += 8)
        tile[ty + i][tx] = W[(size_t)(by + ty + i) * DHID + bx + tx];
    __syncthreads();
#pragma unroll
    for (int i = 0; i < 32; i += 8)
        g_Wt[(size_t)(bx + ty + i) * DIN + by + tx] = tile[tx][ty + i];
}

// ============================================================
// Encoder GEMM, bf16 3-split, cp.async 4-stage (depth-3 prefetch),
// 2 CTAs/SM, race-free ordering:
//   wait_group 2 -> sync -> commit load(t+3) -> compute(t)
// BK=16 (48 k-tiles). Stage: Ah|Al|Bh|Bl, 128 x 24 halves each.
// ============================================================
#define BK     16
#define HS     24                       // halves per row (16 + 8 pad, 48B)
#define PART   (128 * HS)               // halves per matrix part
#define STG_H  (4 * PART)               // halves per stage (12288)
#define NKT    (DIN / BK)               // 48
#define NSTG   4
#define GEMM_SMEM (NSTG * STG_H * sizeof(__nv_bfloat16))   // 98304 B

__device__ __forceinline__ void cp16(__nv_bfloat16* dst, const __nv_bfloat16* src)
{
    unsigned d = (unsigned)__cvta_generic_to_shared(dst);
    asm volatile("cp.async.cg.shared.global [%0], [%1], 16;\n" :: "r"(d), "l"(src));
}

__global__ __launch_bounds__(256, 2)
void gemm_bf16x3(const float* __restrict__ bias, float* __restrict__ C)
{
    extern __shared__ __nv_bfloat16 smh[];   // 4 stages

    int tid  = threadIdx.x;
    int warp = tid >> 5;
    int wm   = warp & 3;
    int wn   = warp >> 2;
    int m0 = blockIdx.y * 128;
    int n0 = blockIdx.x * 128;

    using FragA = wmma::fragment<wmma::matrix_a, 16, 16, 16, __nv_bfloat16, wmma::row_major>;
    using FragB = wmma::fragment<wmma::matrix_b, 16, 16, 16, __nv_bfloat16, wmma::col_major>;
    using FragC = wmma::fragment<wmma::accumulator, 16, 16, 16, float>;

    // ---- bias init via smem f32 broadcast tile (reuses stage region) ----
    float* bsm = (float*)smh;
    for (int i = tid; i < 16 * 128; i += 256)
        bsm[i] = bias[n0 + (i & 127)];
    __syncthreads();

    FragC acc[2][4];
#pragma unroll
    for (int i = 0; i < 2; i++)
#pragma unroll
        for (int j = 0; j < 4; j++)
            wmma::load_matrix_sync(acc[i][j], &bsm[wn * 64 + j * 16], 128, wmma::mem_row_major);
    __syncthreads();

    // per part: 128 rows x 16 halves = 256 cp16 = 1 per thread per part
    int r_ld  = tid >> 1;
    int ch_ld = (tid & 1) * 8;
    auto load_tile = [&](int buf, int kt) {
        __nv_bfloat16* s = smh + buf * STG_H;
        int k0 = kt * BK;
        size_t ga = (size_t)(m0 + r_ld) * DIN + k0 + ch_ld;
        size_t gb = (size_t)(n0 + r_ld) * DIN + k0 + ch_ld;
        cp16(&s[0 * PART + r_ld * HS + ch_ld], &g_Ah[ga]);
        cp16(&s[1 * PART + r_ld * HS + ch_ld], &g_Al[ga]);
        cp16(&s[2 * PART + r_ld * HS + ch_ld], &g_Bh[gb]);
        cp16(&s[3 * PART + r_ld * HS + ch_ld], &g_Bl[gb]);
        asm volatile("cp.async.commit_group;\n" ::);
    };

    // ---- prologue: 3 tiles in flight ----
    load_tile(0, 0);
    load_tile(1, 1);
    load_tile(2, 2);

    for (int t = 0; t < NKT; t++) {
        asm volatile("cp.async.wait_group 2;\n" ::);
        __syncthreads();                 // tile t landed; compute(t-1) done

        if (t + 3 < NKT) load_tile((t + 3) & 3, t + 3);
        else             asm volatile("cp.async.commit_group;\n" ::);

        __nv_bfloat16* s  = smh + (t & 3) * STG_H;
        __nv_bfloat16* Ah = s;
        __nv_bfloat16* Al = s + PART;
        __nv_bfloat16* Bh = s + 2 * PART;
        __nv_bfloat16* Bl = s + 3 * PART;

        FragA ah[2], al[2];
        FragB bh[4];
#pragma unroll
        for (int i = 0; i < 2; i++) {
            wmma::load_matrix_sync(ah[i], &Ah[(wm * 32 + i * 16) * HS], HS);
            wmma::load_matrix_sync(al[i], &Al[(wm * 32 + i * 16) * HS], HS);
        }
#pragma unroll
        for (int j = 0; j < 4; j++)
            wmma::load_matrix_sync(bh[j], &Bh[(wn * 64 + j * 16) * HS], HS);

        // sweep 1: ah x bh
#pragma unroll
        for (int j = 0; j < 4; j++)
#pragma unroll
            for (int i = 0; i < 2; i++)
                wmma::mma_sync(acc[i][j], ah[i], bh[j], acc[i][j]);

        // sweep 2: ah x bl (transient bl)
#pragma unroll
        for (int j = 0; j < 4; j++) {
            FragB bl;
            wmma::load_matrix_sync(bl, &Bl[(wn * 64 + j * 16) * HS], HS);
#pragma unroll
            for (int i = 0; i < 2; i++)
                wmma::mma_sync(acc[i][j], ah[i], bl, acc[i][j]);
        }

        // sweep 3: al x bh
#pragma unroll
        for (int j = 0; j < 4; j++)
#pragma unroll
            for (int i = 0; i < 2; i++)
                wmma::mma_sync(acc[i][j], al[i], bh[j], acc[i][j]);
    }

#pragma unroll
    for (int i = 0; i < 2; i++)
#pragma unroll
        for (int j = 0; j < 4; j++) {
            float* cp = &C[(size_t)(m0 + wm * 32 + i * 16) * DHID + n0 + wn * 64 + j * 16];
            wmma::store_matrix_sync(cp, acc[i][j], DHID, wmma::mem_row_major);
        }
}

// ============================================================
// Top-K with exact fp64 re-ranking of the ambiguous boundary.
// ============================================================
#define AMBIG_W 1e-4f
#define MAXCAND 16

__device__ __forceinline__ float key_decode(unsigned k)
{
    return (k >= 0x80000000u) ? __uint_as_float(k ^ 0x80000000u)
                              : __uint_as_float(~k);
}

__global__ __launch_bounds__(256)
void topk_kernel(const float* __restrict__ hpre, float* __restrict__ hsp,
                 const float* __restrict__ x, const float* __restrict__ Wenc)
{
    int lane = threadIdx.x & 31;
    int warp = threadIdx.x >> 5;
    int row  = blockIdx.x * 8 + warp;
    const float* p = hpre + (size_t)row * DHID;

    __shared__ int    s_cidx[8][MAXCAND];
    __shared__ double s_cval[8][MAXCAND];
    __shared__ int    s_csel[8][MAXCAND];
    __shared__ unsigned s_chosen[8];

    unsigned key[64];
#pragma unroll
    for (int j = 0; j < 64; j++) {
        unsigned u = __float_as_uint(p[j * 32 + lane]);
        key[j] = (u & 0x80000000u) ? ~u : (u | 0x80000000u);
    }

    unsigned lmax = 0u;
#pragma unroll
    for (int j = 0; j < 64; j++) lmax = (key[j] > lmax) ? key[j] : lmax;
    unsigned lo = __reduce_min_sync(0xFFFFFFFFu, lmax);
    unsigned hi = __reduce_max_sync(0xFFFFFFFFu, lmax);

#pragma unroll 1
    for (int it = 0; it < 32; ++it) {
        if (lo >= hi) break;
        unsigned span = hi - lo;
        unsigned mid = lo + (span >> 1) + (span & 1u);
        int c = 0;
#pragma unroll
        for (int j = 0; j < 64; j++) c += (key[j] >= mid) ? 1 : 0;
        c = __reduce_add_sync(0xFFFFFFFFu, c);
        if (c >= TOPK) lo = mid; else hi = mid - 1;
    }
    unsigned T = lo;

    int cg = 0;
#pragma unroll
    for (int j = 0; j < 64; j++) cg += (key[j] > T) ? 1 : 0;
    cg = __reduce_add_sync(0xFFFFFFFFu, cg);
    int rem = TOPK - cg;

    unsigned lmask = (1u << lane) - 1u;
    unsigned long long selmask = 0ull;
    unsigned kmin_in = 0xFFFFFFFFu;
    unsigned kmax_out = 0u;
#pragma unroll 1
    for (int j = 0; j < 64; j++) {
        unsigned k = key[j];
        bool eq = (k == T);
        unsigned em = __ballot_sync(0xFFFFFFFFu, eq);
        bool pick = eq && ((int)__popc(em & lmask) < rem);
        bool sel  = (k > T) || pick;
        if (sel) { selmask |= (1ull << j); if (k < kmin_in) kmin_in = k; }
        else     { if (k > kmax_out) kmax_out = k; }
        rem -= __popc(em);
        if (rem < 0) rem = 0;
    }
    kmin_in  = __reduce_min_sync(0xFFFFFFFFu, kmin_in);
    kmax_out = __reduce_max_sync(0xFFFFFFFFu, kmax_out);

    float vin  = key_decode(kmin_in);
    float vout = key_decode(kmax_out);

    if (vin - vout < AMBIG_W) {
        float wlo = vout - AMBIG_W;
        float whi = vin + AMBIG_W;
        int ncand = 0;
#pragma unroll 1
        for (int j = 0; j < 64; j++) {
            float v = key_decode(key[j]);
            bool isc = (v >= wlo) && (v <= whi);
            unsigned bal = __ballot_sync(0xFFFFFFFFu, isc);
            if (isc) {
                int pos = ncand + __popc(bal & lmask);
                if (pos < MAXCAND) {
                    s_cidx[warp][pos] = j * 32 + lane;
                    s_csel[warp][pos] = (int)((selmask >> j) & 1ull);
                }
            }
            ncand += __popc(bal);
        }
        if (ncand > MAXCAND) ncand = MAXCAND;
        __syncwarp();

        const float* xr = x + (size_t)row * DIN;
        for (int c = 0; c < ncand; c++) {
            const float* wr = Wenc + (size_t)s_cidx[warp][c] * DIN;
            double s = 0.0;
#pragma unroll
            for (int t = 0; t < DIN / 32; t++) {
                int kk = lane + t * 32;
                s += (double)xr[kk] * (double)wr[kk];
            }
#pragma unroll
            for (int off = 16; off > 0; off >>= 1)
                s += __shfl_down_sync(0xFFFFFFFFu, s, off);
            if (lane == 0) s_cval[warp][c] = s;
            __syncwarp();
        }

        if (lane == 0) {
            int nkeep = 0;
            for (int c = 0; c < ncand; c++) nkeep += s_csel[warp][c];
            unsigned chosen = 0;
            for (int s = 0; s < nkeep; s++) {
                int best = -1;
                for (int c = 0; c < ncand; c++) {
                    if (chosen & (1u << c)) continue;
                    if (best < 0 ||
                        s_cval[warp][c] > s_cval[warp][best] ||
                        (s_cval[warp][c] == s_cval[warp][best] &&
                         s_cidx[warp][c] < s_cidx[warp][best]))
                        best = c;
                }
                chosen |= (1u << best);
            }
            s_chosen[warp] = chosen;
        }
        __syncwarp();
        unsigned chosen = s_chosen[warp];

        for (int c = 0; c < ncand; c++) {
            int fi = s_cidx[warp][c];
            if ((fi & 31) == lane) {
                int j = fi >> 5;
                if (chosen & (1u << c)) selmask |=  (1ull << j);
                else                    selmask &= ~(1ull << j);
            }
        }
        __syncwarp();
    }

    float* orow = hsp + (size_t)row * DHID;
    int nsel = 0;
#pragma unroll 1
    for (int j = 0; j < 64; j++) {
        bool sel = (selmask >> j) & 1ull;
        unsigned k = key[j];
        float v = (k > 0x80000000u) ? __uint_as_float(k ^ 0x80000000u) : 0.0f;
        orow[j * 32 + lane] = sel ? v : 0.0f;

        unsigned sm2 = __ballot_sync(0xFFFFFFFFu, sel);
        if (sel) {
            int slot = nsel + __popc(sm2 & lmask);
            g_tidx[(size_t)row * TOPK + slot] = j * 32 + lane;
            g_tval[(size_t)row * TOPK + slot] = v;
        }
        nsel += __popc(sm2);
    }
}

// ============================================================
// Sparse decoder: recon[row,:] = b_dec + sum_k val_k * Wt[idx_k,:]
// ============================================================
__global__ __launch_bounds__(192)
void decode_kernel(const float* __restrict__ bdec, float* __restrict__ recon)
{
    int row = blockIdx.x;
    int t = threadIdx.x;
    __shared__ float sval[TOPK];
    __shared__ int   sidx[TOPK];
    if (t < TOPK) {
        sval[t] = g_tval[(size_t)row * TOPK + t];
        sidx[t] = g_tidx[(size_t)row * TOPK + t];
    }
    __syncthreads();

    float4 acc = *(const float4*)&bdec[t * 4];
#pragma unroll 8
    for (int k = 0; k < TOPK; k++) {
        float v = sval[k];
        float4 w = *(const float4*)&g_Wt[(size_t)sidx[k] * DIN + t * 4];
        acc.x += v * w.x; acc.y += v * w.y; acc.z += v * w.z; acc.w += v * w.w;
    }
    *(float4*)&recon[(size_t)row * DIN + t * 4] = acc;
}

// ============================================================
extern "C" void kernel_launch(void* const* d_in, const int* in_sizes, int n_in,
                              void* d_out, int out_size)
{
    const float* x     = (const float*)d_in[0];
    const float* W_enc = (const float*)d_in[1];
    const float* b_enc = (const float*)d_in[2];
    const float* W_dec = (const float*)d_in[3];
    const float* b_dec = (const float*)d_in[4];

    float* out   = (float*)d_out;
    float* recon = out;                                 // [B, 768]
    float* hsp   = out + (size_t)BATCH * DIN;           // [B, 2048]
    float* hpre  = hsp + (size_t)BATCH * DHID;          // [B, 2048]

    __nv_bfloat16 *ah, *al, *bh, *bl;
    cudaGetSymbolAddress((void**)&ah, g_Ah);
    cudaGetSymbolAddress((void**)&al, g_Al);
    cudaGetSymbolAddress((void**)&bh, g_Bh);
    cudaGetSymbolAddress((void**)&bl, g_Bl);

    cudaFuncSetAttribute(gemm_bf16x3, cudaFuncAttributeMaxDynamicSharedMemorySize,
                         (int)GEMM_SMEM);

    split_kernel<<<(BATCH * DIN / 2) / 256, 256>>>(x, ah, al);
    split_kernel<<<(DHID * DIN / 2) / 256, 256>>>(W_enc, bh, bl);
    transpose_kernel<<<dim3(DHID / 32, DIN / 32), dim3(32, 8)>>>(W_dec);
    gemm_bf16x3<<<dim3(DHID / 128, BATCH / 128), 256, GEMM_SMEM>>>(b_enc, hpre);
    topk_kernel<<<BATCH / 8, 256>>>(hpre, hsp, x, W_enc);
    decode_kernel<<<BATCH, 192>>>(b_dec, recon);
}

// round 11
// speedup vs baseline: 1.1012x; 1.1012x over previous
#include <cuda_runtime.h>
#include <cuda_bf16.h>
#include <cuda_fp16.h>
#include <mma.h>
#include <cstdint>

using namespace nvcuda;

#define BATCH 32768
#define DIN   768
#define DHID  2048
#define TOPK  32

// -------- scratch (no cudaMalloc allowed) --------
__device__ __align__(16) float g_Wt[(size_t)DHID * DIN];   // W_dec^T [2048][768]
__device__ int   g_tidx[(size_t)BATCH * TOPK];
__device__ float g_tval[(size_t)BATCH * TOPK];
__device__ __align__(16) __nv_bfloat16 g_Ah[(size_t)BATCH * DIN];
__device__ __align__(16) __nv_bfloat16 g_Al[(size_t)BATCH * DIN];
__device__ __align__(16) __nv_bfloat16 g_Bh[(size_t)DHID * DIN];
__device__ __align__(16) __nv_bfloat16 g_Bl[(size_t)DHID * DIN];

// ============================================================
// f32 -> (hi, lo) bf16 split
// ============================================================
__global__ __launch_bounds__(256)
void split_kernel(const float* __restrict__ src,
                  __nv_bfloat16* __restrict__ hi,
                  __nv_bfloat16* __restrict__ lo)
{
    int i = blockIdx.x * 256 + threadIdx.x;
    float2 v = ((const float2*)src)[i];
    __nv_bfloat16 h0 = __float2bfloat16(v.x);
    __nv_bfloat16 h1 = __float2bfloat16(v.y);
    __nv_bfloat16 l0 = __float2bfloat16(v.x - __bfloat162float(h0));
    __nv_bfloat16 l1 = __float2bfloat16(v.y - __bfloat162float(h1));
    ((__nv_bfloat162*)hi)[i] = __halves2bfloat162(h0, h1);
    ((__nv_bfloat162*)lo)[i] = __halves2bfloat162(l0, l1);
}

// ============================================================
// W_dec [768][2048] -> g_Wt [2048][768]
// ============================================================
__global__ void transpose_kernel(const float* __restrict__ W)
{
    __shared__ float tile[32][33];
    int bx = blockIdx.x * 32, by = blockIdx.y * 32;
    int tx = threadIdx.x, ty = threadIdx.y;
#pragma unroll
    for (int i = 0; i < 32; i += 8)
        tile[ty + i][tx] = W[(size_t)(by + ty + i) * DHID + bx + tx];
    __syncthreads();
#pragma unroll
    for (int i = 0; i < 32; i += 8)
        g_Wt[(size_t)(bx + ty + i) * DIN + by + tx] = tile[tx][ty + i];
}

// ============================================================
// Encoder GEMM (R8 config, best measured): bf16 3-split,
// cp.async 2-stage, 2 CTAs/SM, BK=32, term sweeps.
// ============================================================
#define BK     32
#define HS     40                       // halves per row (32 + 8 pad)
#define PART   (128 * HS)
#define STG_H  (4 * PART)
#define NKT    (DIN / BK)               // 24
#define GEMM_SMEM (2 * STG_H * sizeof(__nv_bfloat16))   // 81920 B

__device__ __forceinline__ void cp16(__nv_bfloat16* dst, const __nv_bfloat16* src)
{
    unsigned d = (unsigned)__cvta_generic_to_shared(dst);
    asm volatile("cp.async.cg.shared.global [%0], [%1], 16;\n" :: "r"(d), "l"(src));
}

__global__ __launch_bounds__(256, 2)
void gemm_bf16x3(const float* __restrict__ bias, float* __restrict__ C)
{
    extern __shared__ __nv_bfloat16 smh[];

    int tid  = threadIdx.x;
    int warp = tid >> 5;
    int wm   = warp & 3;
    int wn   = warp >> 2;
    int m0 = blockIdx.y * 128;
    int n0 = blockIdx.x * 128;

    using FragA = wmma::fragment<wmma::matrix_a, 16, 16, 16, __nv_bfloat16, wmma::row_major>;
    using FragB = wmma::fragment<wmma::matrix_b, 16, 16, 16, __nv_bfloat16, wmma::col_major>;
    using FragC = wmma::fragment<wmma::accumulator, 16, 16, 16, float>;

    float* bsm = (float*)smh;
    for (int i = tid; i < 16 * 128; i += 256)
        bsm[i] = bias[n0 + (i & 127)];
    __syncthreads();

    FragC acc[2][4];
#pragma unroll
    for (int i = 0; i < 2; i++)
#pragma unroll
        for (int j = 0; j < 4; j++)
            wmma::load_matrix_sync(acc[i][j], &bsm[wn * 64 + j * 16], 128, wmma::mem_row_major);
    __syncthreads();

    auto load_tile = [&](int buf, int kt) {
        __nv_bfloat16* s = smh + buf * STG_H;
        int k0 = kt * BK;
#pragma unroll
        for (int p = 0; p < 2; p++) {
            int f  = tid + p * 256;
            int r  = f >> 2;
            int ch = (f & 3) * 8;
            size_t ga = (size_t)(m0 + r) * DIN + k0 + ch;
            size_t gb = (size_t)(n0 + r) * DIN + k0 + ch;
            cp16(&s[0 * PART + r * HS + ch], &g_Ah[ga]);
            cp16(&s[1 * PART + r * HS + ch], &g_Al[ga]);
            cp16(&s[2 * PART + r * HS + ch], &g_Bh[gb]);
            cp16(&s[3 * PART + r * HS + ch], &g_Bl[gb]);
        }
        asm volatile("cp.async.commit_group;\n" ::);
    };

    load_tile(0, 0);

    for (int t = 0; t < NKT; t++) {
        if (t + 1 < NKT) load_tile((t + 1) & 1, t + 1);
        else             asm volatile("cp.async.commit_group;\n" ::);

        asm volatile("cp.async.wait_group 1;\n" ::);
        __syncthreads();

        __nv_bfloat16* s  = smh + (t & 1) * STG_H;
        __nv_bfloat16* Ah = s;
        __nv_bfloat16* Al = s + PART;
        __nv_bfloat16* Bh = s + 2 * PART;
        __nv_bfloat16* Bl = s + 3 * PART;

#pragma unroll
        for (int ks = 0; ks < BK; ks += 16) {
            FragA ah[2], al[2];
            FragB bh[4];
#pragma unroll
            for (int i = 0; i < 2; i++) {
                wmma::load_matrix_sync(ah[i], &Ah[(wm * 32 + i * 16) * HS + ks], HS);
                wmma::load_matrix_sync(al[i], &Al[(wm * 32 + i * 16) * HS + ks], HS);
            }
#pragma unroll
            for (int j = 0; j < 4; j++)
                wmma::load_matrix_sync(bh[j], &Bh[(wn * 64 + j * 16) * HS + ks], HS);

#pragma unroll
            for (int j = 0; j < 4; j++)
#pragma unroll
                for (int i = 0; i < 2; i++)
                    wmma::mma_sync(acc[i][j], ah[i], bh[j], acc[i][j]);

#pragma unroll
            for (int j = 0; j < 4; j++) {
                FragB bl;
                wmma::load_matrix_sync(bl, &Bl[(wn * 64 + j * 16) * HS + ks], HS);
#pragma unroll
                for (int i = 0; i < 2; i++)
                    wmma::mma_sync(acc[i][j], ah[i], bl, acc[i][j]);
            }

#pragma unroll
            for (int j = 0; j < 4; j++)
#pragma unroll
                for (int i = 0; i < 2; i++)
                    wmma::mma_sync(acc[i][j], al[i], bh[j], acc[i][j]);
        }
        __syncthreads();
    }

#pragma unroll
    for (int i = 0; i < 2; i++)
#pragma unroll
        for (int j = 0; j < 4; j++) {
            float* cp = &C[(size_t)(m0 + wm * 32 + i * 16) * DHID + n0 + wn * 64 + j * 16];
            wmma::store_matrix_sync(cp, acc[i][j], DHID, wmma::mem_row_major);
        }
}

// ============================================================
// Top-K v2: fp16x2 SIMD counting + exact fp32 tie ranking +
// fp64 rescue of the ambiguous boundary. One warp per row.
// Selection is bit-identical to exact fp32 top-32 (idx tiebreak).
// ============================================================
#define AMBIG_W 1e-4f
#define MAXCAND 16
#define MAXTIE  32

__device__ __forceinline__ unsigned fmono(float f)
{
    unsigned u = __float_as_uint(f);
    return (u & 0x80000000u) ? ~u : (u | 0x80000000u);
}

__global__ __launch_bounds__(256, 2)
void topk_kernel(const float* __restrict__ hpre, float* __restrict__ hsp,
                 const float* __restrict__ x, const float* __restrict__ Wenc)
{
    int lane = threadIdx.x & 31;
    int warp = threadIdx.x >> 5;
    int row  = blockIdx.x * 8 + warp;
    const float* p = hpre + (size_t)row * DHID;
    unsigned lmask = (1u << lane) - 1u;

    __shared__ int    s_cidx[8][MAXCAND];
    __shared__ double s_cval[8][MAXCAND];
    __shared__ int    s_csel[8][MAXCAND];
    __shared__ unsigned s_chosen[8];
    __shared__ int    s_tidx[8][MAXTIE];   // tie feature idx
    __shared__ float  s_tval[8][MAXTIE];   // tie fp32 value
    __shared__ int    s_texc[8][MAXTIE];   // excluded feature idx
    __shared__ int    s_nexc[8];

    // ---- load 64 fp32 values; build 32 packed half2 keys ----
    float val[64];
    unsigned hk[32];
    float vmax = -3.0e38f;
#pragma unroll
    for (int r = 0; r < 32; r++) {
        float v0 = p[(2 * r) * 32 + lane];
        float v1 = p[(2 * r + 1) * 32 + lane];
        val[2 * r] = v0; val[2 * r + 1] = v1;
        __half2 h2 = __floats2half2_rn(v0, v1);
        hk[r] = *(unsigned*)&h2;
        vmax = fmaxf(vmax, fmaxf(v0, v1));
    }

    // ---- search bounds from per-lane maxes (mono-u16 of half) ----
    unsigned short hbm = __half_as_ushort(__float2half_rn(vmax));
    unsigned monom = (hbm & 0x8000u) ? (unsigned)(~hbm & 0xFFFFu)
                                     : (unsigned)(hbm | 0x8000u);
    unsigned lo = __reduce_min_sync(0xFFFFFFFFu, monom);
    unsigned hi = __reduce_max_sync(0xFFFFFFFFu, monom);
    if (lo < 0x8001u) lo = 0x8001u;

    // count(#halves >= half_from_bits(tb)), tb positive
    auto count_ge = [&](unsigned tb) -> int {
        __half hval = __ushort_as_half((unsigned short)tb);
        __half2 t2 = __half2half2(hval);
        __half2 c2 = __float2half2_rn(0.0f);
#pragma unroll
        for (int r = 0; r < 32; r++)
            c2 = __hadd2(c2, __hge2(*(__half2*)&hk[r], t2));
        int c = (int)(__low2float(c2) + __high2float(c2));
        return __reduce_add_sync(0xFFFFFFFFu, c);
    };

    unsigned T_hb;
    int excess = 0;
    bool degenerate = false;

    if (hi < 0x8001u) {
        degenerate = true;           // no positive halves at all
        T_hb = 1;
    } else {
        int c0 = count_ge(lo & 0x7FFFu);
        if (c0 < TOPK) {
            degenerate = true;       // fewer than 32 positives
            T_hb = 1;
        } else {
#pragma unroll 1
            for (int it = 0; it < 16; ++it) {
                if (lo >= hi) break;
                unsigned span = hi - lo;
                unsigned mid = lo + (span >> 1) + (span & 1u);
                int c = count_ge(mid & 0x7FFFu);
                if (c >= TOPK) lo = mid; else hi = mid - 1;
            }
            T_hb = lo & 0x7FFFu;
            int cT = count_ge(T_hb);
            excess = cT - TOPK;
        }
    }

    // ---- rank ties by exact fp32 (desc) / idx (asc) if needed ----
    int nexc = 0;
    if (!degenerate && excess > 0) {
        int nt = 0;
#pragma unroll 1
        for (int j = 0; j < 64; j++) {
            unsigned hb = (hk[j >> 1] >> ((j & 1) * 16)) & 0xFFFFu;
            bool tie = (hb == T_hb);
            unsigned bal = __ballot_sync(0xFFFFFFFFu, tie);
            if (tie) {
                int pos = nt + __popc(bal & lmask);
                if (pos < MAXTIE) {
                    s_tidx[warp][pos] = j * 32 + lane;
                    s_tval[warp][pos] = val[j];
                }
            }
            nt += __popc(bal);
        }
        if (nt > MAXTIE) nt = MAXTIE;
        __syncwarp();
        if (lane == 0) {
            int ne = excess; if (ne > nt) ne = nt;
            unsigned used = 0;
            for (int e = 0; e < ne; e++) {
                int worst = -1;
                for (int c = 0; c < nt; c++) {
                    if (used & (1u << c)) continue;
                    if (worst < 0 ||
                        s_tval[warp][c] < s_tval[warp][worst] ||
                        (s_tval[warp][c] == s_tval[warp][worst] &&
                         s_tidx[warp][c] > s_tidx[warp][worst]))
                        worst = c;
                }
                used |= (1u << worst);
                s_texc[warp][e] = s_tidx[warp][worst];
            }
            s_nexc[warp] = ne;
        }
        __syncwarp();
        nexc = s_nexc[warp];
    }

    // ---- build selection mask; track fp32 vin/vout ----
    unsigned long long selmask = 0ull;
    float vin = 3.0e38f, vout = -3.0e38f;
#pragma unroll 1
    for (int j = 0; j < 64; j++) {
        unsigned hb = (hk[j >> 1] >> ((j & 1) * 16)) & 0xFFFFu;
        bool sel = (hb < 0x8000u) && (hb >= T_hb);
        if (sel && nexc > 0 && hb == T_hb) {
            int fi = j * 32 + lane;
            for (int e = 0; e < nexc; e++)
                if (s_texc[warp][e] == fi) { sel = false; break; }
        }
        if (sel) { selmask |= (1ull << j); vin = fminf(vin, val[j]); }
        else     { vout = fmaxf(vout, val[j]); }
    }
    int nsel_total = __reduce_add_sync(0xFFFFFFFFu, __popcll(selmask));
    vin  = __uint_as_float(0);   // placeholder overwritten below
    {
        // warp-reduce vin (min) and vout (max) via monotone uints
        float vin_l = 3.0e38f, vout_l = -3.0e38f;
#pragma unroll
        for (int j = 0; j < 64; j++) {
            if ((selmask >> j) & 1ull) vin_l = fminf(vin_l, val[j]);
            else                       vout_l = fmaxf(vout_l, val[j]);
        }
        unsigned vi = __reduce_min_sync(0xFFFFFFFFu, fmono(vin_l));
        unsigned vo = __reduce_max_sync(0xFFFFFFFFu, fmono(vout_l));
        vin  = (vi >= 0x80000000u) ? __uint_as_float(vi ^ 0x80000000u) : __uint_as_float(~vi);
        vout = (vo >= 0x80000000u) ? __uint_as_float(vo ^ 0x80000000u) : __uint_as_float(~vo);
    }

    // ---- fp64 rescue of ambiguous boundary (selection exactness) ----
    if (nsel_total == TOPK && vin - vout < AMBIG_W) {
        float wlo = vout - AMBIG_W;
        float whi = vin + AMBIG_W;
        int ncand = 0;
#pragma unroll 1
        for (int j = 0; j < 64; j++) {
            float v = val[j];
            bool isc = (v >= wlo) && (v <= whi);
            unsigned bal = __ballot_sync(0xFFFFFFFFu, isc);
            if (isc) {
                int pos = ncand + __popc(bal & lmask);
                if (pos < MAXCAND) {
                    s_cidx[warp][pos] = j * 32 + lane;
                    s_csel[warp][pos] = (int)((selmask >> j) & 1ull);
                }
            }
            ncand += __popc(bal);
        }
        if (ncand > MAXCAND) ncand = MAXCAND;
        __syncwarp();

        const float* xr = x + (size_t)row * DIN;
        for (int c = 0; c < ncand; c++) {
            const float* wr = Wenc + (size_t)s_cidx[warp][c] * DIN;
            double s = 0.0;
#pragma unroll
            for (int t = 0; t < DIN / 32; t++) {
                int kk = lane + t * 32;
                s += (double)xr[kk] * (double)wr[kk];
            }
#pragma unroll
            for (int off = 16; off > 0; off >>= 1)
                s += __shfl_down_sync(0xFFFFFFFFu, s, off);
            if (lane == 0) s_cval[warp][c] = s;
            __syncwarp();
        }

        if (lane == 0) {
            int nkeep = 0;
            for (int c = 0; c < ncand; c++) nkeep += s_csel[warp][c];
            unsigned chosen = 0;
            for (int s = 0; s < nkeep; s++) {
                int best = -1;
                for (int c = 0; c < ncand; c++) {
                    if (chosen & (1u << c)) continue;
                    if (best < 0 ||
                        s_cval[warp][c] > s_cval[warp][best] ||
                        (s_cval[warp][c] == s_cval[warp][best] &&
                         s_cidx[warp][c] < s_cidx[warp][best]))
                        best = c;
                }
                chosen |= (1u << best);
            }
            s_chosen[warp] = chosen;
        }
        __syncwarp();
        unsigned chosen = s_chosen[warp];

        for (int c = 0; c < ncand; c++) {
            int fi = s_cidx[warp][c];
            if ((fi & 31) == lane) {
                int j = fi >> 5;
                if (chosen & (1u << c)) selmask |=  (1ull << j);
                else                    selmask &= ~(1ull << j);
            }
        }
        __syncwarp();
    }

    // ---- write dense h_sparse + compact lists ----
    float* orow = hsp + (size_t)row * DHID;
    int nsel = 0;
#pragma unroll 1
    for (int j = 0; j < 64; j++) {
        bool sel = (selmask >> j) & 1ull;
        float v = fmaxf(val[j], 0.0f);   // relu
        orow[j * 32 + lane] = sel ? v : 0.0f;

        unsigned sm2 = __ballot_sync(0xFFFFFFFFu, sel);
        if (sel) {
            int slot = nsel + __popc(sm2 & lmask);
            if (slot < TOPK) {
                g_tidx[(size_t)row * TOPK + slot] = j * 32 + lane;
                g_tval[(size_t)row * TOPK + slot] = v;
            }
        }
        nsel += __popc(sm2);
    }
    // pad compact list in (never-expected) degenerate case
    if (nsel < TOPK && lane == 0) {
        for (int s = nsel; s < TOPK; s++) {
            g_tidx[(size_t)row * TOPK + s] = 0;
            g_tval[(size_t)row * TOPK + s] = 0.0f;
        }
    }
}

// ============================================================
// Sparse decoder: recon[row,:] = b_dec + sum_k val_k * Wt[idx_k,:]
// ============================================================
__global__ __launch_bounds__(192)
void decode_kernel(const float* __restrict__ bdec, float* __restrict__ recon)
{
    int row = blockIdx.x;
    int t = threadIdx.x;
    __shared__ float sval[TOPK];
    __shared__ int   sidx[TOPK];
    if (t < TOPK) {
        sval[t] = g_tval[(size_t)row * TOPK + t];
        sidx[t] = g_tidx[(size_t)row * TOPK + t];
    }
    __syncthreads();

    float4 acc = *(const float4*)&bdec[t * 4];
#pragma unroll 8
    for (int k = 0; k < TOPK; k++) {
        float v = sval[k];
        float4 w = *(const float4*)&g_Wt[(size_t)sidx[k] * DIN + t * 4];
        acc.x += v * w.x; acc.y += v * w.y; acc.z += v * w.z; acc.w += v * w.w;
    }
    *(float4*)&recon[(size_t)row * DIN + t * 4] = acc;
}

// ============================================================
extern "C" void kernel_launch(void* const* d_in, const int* in_sizes, int n_in,
                              void* d_out, int out_size)
{
    const float* x     = (const float*)d_in[0];
    const float* W_enc = (const float*)d_in[1];
    const float* b_enc = (const float*)d_in[2];
    const float* W_dec = (const float*)d_in[3];
    const float* b_dec = (const float*)d_in[4];

    float* out   = (float*)d_out;
    float* recon = out;                                 // [B, 768]
    float* hsp   = out + (size_t)BATCH * DIN;           // [B, 2048]
    float* hpre  = hsp + (size_t)BATCH * DHID;          // [B, 2048]

    __nv_bfloat16 *ah, *al, *bh, *bl;
    cudaGetSymbolAddress((void**)&ah, g_Ah);
    cudaGetSymbolAddress((void**)&al, g_Al);
    cudaGetSymbolAddress((void**)&bh, g_Bh);
    cudaGetSymbolAddress((void**)&bl, g_Bl);

    cudaFuncSetAttribute(gemm_bf16x3, cudaFuncAttributeMaxDynamicSharedMemorySize,
                         (int)GEMM_SMEM);

    split_kernel<<<(BATCH * DIN / 2) / 256, 256>>>(x, ah, al);
    split_kernel<<<(DHID * DIN / 2) / 256, 256>>>(W_enc, bh, bl);
    transpose_kernel<<<dim3(DHID / 32, DIN / 32), dim3(32, 8)>>>(W_dec);
    gemm_bf16x3<<<dim3(DHID / 128, BATCH / 128), 256, GEMM_SMEM>>>(b_enc, hpre);
    topk_kernel<<<BATCH / 8, 256>>>(hpre, hsp, x, W_enc);
    decode_kernel<<<BATCH, 192>>>(b_dec, recon);
}

// round 12
// speedup vs baseline: 1.3636x; 1.2383x over previous
#include <cuda_runtime.h>
#include <cuda_fp16.h>
#include <mma.h>
#include <cstdint>

using namespace nvcuda;

#define BATCH 32768
#define DIN   768
#define DHID  2048
#define TOPK  32

// -------- scratch (no cudaMalloc allowed) --------
__device__ __align__(16) float g_Wt[(size_t)DHID * DIN];   // W_dec^T [2048][768]
__device__ int   g_tidx[(size_t)BATCH * TOPK];
__device__ float g_tval[(size_t)BATCH * TOPK];
__device__ __align__(16) __half g_Ah[(size_t)BATCH * DIN];  // x rounded to fp16
__device__ __align__(16) __half g_Bh[(size_t)DHID * DIN];   // W_enc hi (fp16)
__device__ __align__(16) __half g_Bl[(size_t)DHID * DIN];   // W_enc lo (fp16)

// ============================================================
// x -> fp16 round
// ============================================================
__global__ __launch_bounds__(256)
void round_x_kernel(const float* __restrict__ src, __half* __restrict__ dst)
{
    int i = blockIdx.x * 256 + threadIdx.x;
    float2 v = ((const float2*)src)[i];
    ((__half2*)dst)[i] = __floats2half2_rn(v.x, v.y);
}

// ============================================================
// W_enc -> (hi, lo) fp16 split
// ============================================================
__global__ __launch_bounds__(256)
void split_w_kernel(const float* __restrict__ src,
                    __half* __restrict__ hi, __half* __restrict__ lo)
{
    int i = blockIdx.x * 256 + threadIdx.x;
    float2 v = ((const float2*)src)[i];
    __half h0 = __float2half_rn(v.x);
    __half h1 = __float2half_rn(v.y);
    __half l0 = __float2half_rn(v.x - __half2float(h0));
    __half l1 = __float2half_rn(v.y - __half2float(h1));
    ((__half2*)hi)[i] = __halves2half2(h0, h1);
    ((__half2*)lo)[i] = __halves2half2(l0, l1);
}

// ============================================================
// W_dec [768][2048] -> g_Wt [2048][768]
// ============================================================
__global__ void transpose_kernel(const float* __restrict__ W)
{
    __shared__ float tile[32][33];
    int bx = blockIdx.x * 32, by = blockIdx.y * 32;
    int tx = threadIdx.x, ty = threadIdx.y;
#pragma unroll
    for (int i = 0; i < 32; i += 8)
        tile[ty + i][tx] = W[(size_t)(by + ty + i) * DHID + bx + tx];
    __syncthreads();
#pragma unroll
    for (int i = 0; i < 32; i += 8)
        g_Wt[(size_t)(bx + ty + i) * DIN + by + tx] = tile[tx][ty + i];
}

// ============================================================
// Encoder GEMM, fp16 2-term (h = ah*bh + ah*bl), cp.async
// 2-stage, 2 CTAs/SM. Block 128x128, BK=32, 8 warps (Wm=2,Wn=4),
// warp tile 64x32. Stage: Ah|Bh|Bl, 128 x 40 halves each.
// ============================================================
#define BK     32
#define HS     40                       // halves per row (32 + 8 pad)
#define PART   (128 * HS)
#define STG_H  (3 * PART)
#define NKT    (DIN / BK)               // 24
#define GEMM_SMEM (2 * STG_H * sizeof(__half))   // 61440 B

__device__ __forceinline__ void cp16(__half* dst, const __half* src)
{
    unsigned d = (unsigned)__cvta_generic_to_shared(dst);
    asm volatile("cp.async.cg.shared.global [%0], [%1], 16;\n" :: "r"(d), "l"(src));
}

__global__ __launch_bounds__(256, 2)
void gemm_fp16x2(const float* __restrict__ bias, float* __restrict__ C)
{
    extern __shared__ __half smh[];

    int tid  = threadIdx.x;
    int warp = tid >> 5;
    int wm   = warp & 1;        // 0..1 : 64-row M slab
    int wn   = warp >> 1;       // 0..3 : 32-col N slab
    int m0 = blockIdx.y * 128;
    int n0 = blockIdx.x * 128;

    using FragA = wmma::fragment<wmma::matrix_a, 16, 16, 16, __half, wmma::row_major>;
    using FragB = wmma::fragment<wmma::matrix_b, 16, 16, 16, __half, wmma::col_major>;
    using FragC = wmma::fragment<wmma::accumulator, 16, 16, 16, float>;

    // ---- bias init via smem f32 broadcast tile (reuses stage region) ----
    float* bsm = (float*)smh;
    for (int i = tid; i < 16 * 128; i += 256)
        bsm[i] = bias[n0 + (i & 127)];
    __syncthreads();

    FragC acc[4][2];
#pragma unroll
    for (int i = 0; i < 4; i++)
#pragma unroll
        for (int j = 0; j < 2; j++)
            wmma::load_matrix_sync(acc[i][j], &bsm[wn * 32 + j * 16], 128, wmma::mem_row_major);
    __syncthreads();

    auto load_tile = [&](int buf, int kt) {
        __half* s = smh + buf * STG_H;
        int k0 = kt * BK;
#pragma unroll
        for (int p = 0; p < 2; p++) {
            int f  = tid + p * 256;      // 0..511
            int r  = f >> 2;             // 0..127
            int ch = (f & 3) * 8;        // halves offset 0,8,16,24
            size_t ga = (size_t)(m0 + r) * DIN + k0 + ch;
            size_t gb = (size_t)(n0 + r) * DIN + k0 + ch;
            cp16(&s[0 * PART + r * HS + ch], &g_Ah[ga]);
            cp16(&s[1 * PART + r * HS + ch], &g_Bh[gb]);
            cp16(&s[2 * PART + r * HS + ch], &g_Bl[gb]);
        }
        asm volatile("cp.async.commit_group;\n" ::);
    };

    load_tile(0, 0);

    for (int t = 0; t < NKT; t++) {
        if (t + 1 < NKT) load_tile((t + 1) & 1, t + 1);
        else             asm volatile("cp.async.commit_group;\n" ::);

        asm volatile("cp.async.wait_group 1;\n" ::);
        __syncthreads();

        __half* s  = smh + (t & 1) * STG_H;
        __half* Ah = s;
        __half* Bh = s + PART;
        __half* Bl = s + 2 * PART;

#pragma unroll
        for (int ks = 0; ks < BK; ks += 16) {
            FragB bh[2], bl[2];
#pragma unroll
            for (int j = 0; j < 2; j++) {
                wmma::load_matrix_sync(bh[j], &Bh[(wn * 32 + j * 16) * HS + ks], HS);
                wmma::load_matrix_sync(bl[j], &Bl[(wn * 32 + j * 16) * HS + ks], HS);
            }
#pragma unroll
            for (int i = 0; i < 4; i++) {
                FragA ah;
                wmma::load_matrix_sync(ah, &Ah[(wm * 64 + i * 16) * HS + ks], HS);
#pragma unroll
                for (int j = 0; j < 2; j++)
                    wmma::mma_sync(acc[i][j], ah, bh[j], acc[i][j]);
#pragma unroll
                for (int j = 0; j < 2; j++)
                    wmma::mma_sync(acc[i][j], ah, bl[j], acc[i][j]);
            }
        }
        __syncthreads();
    }

#pragma unroll
    for (int i = 0; i < 4; i++)
#pragma unroll
        for (int j = 0; j < 2; j++) {
            float* cp = &C[(size_t)(m0 + wm * 64 + i * 16) * DHID + n0 + wn * 32 + j * 16];
            wmma::store_matrix_sync(cp, acc[i][j], DHID, wmma::mem_row_major);
        }
}

// ============================================================
// Top-K (R8 version) with exact fp64 re-ranking of the
// ambiguous boundary; window widened to cover fp16-GEMM noise.
// ============================================================
#define AMBIG_W 1e-3f
#define MAXCAND 16

__device__ __forceinline__ float key_decode(unsigned k)
{
    return (k >= 0x80000000u) ? __uint_as_float(k ^ 0x80000000u)
                              : __uint_as_float(~k);
}

__global__ __launch_bounds__(256)
void topk_kernel(const float* __restrict__ hpre, float* __restrict__ hsp,
                 const float* __restrict__ x, const float* __restrict__ Wenc)
{
    int lane = threadIdx.x & 31;
    int warp = threadIdx.x >> 5;
    int row  = blockIdx.x * 8 + warp;
    const float* p = hpre + (size_t)row * DHID;

    __shared__ int    s_cidx[8][MAXCAND];
    __shared__ double s_cval[8][MAXCAND];
    __shared__ int    s_csel[8][MAXCAND];
    __shared__ unsigned s_chosen[8];

    unsigned key[64];
#pragma unroll
    for (int j = 0; j < 64; j++) {
        unsigned u = __float_as_uint(p[j * 32 + lane]);
        key[j] = (u & 0x80000000u) ? ~u : (u | 0x80000000u);
    }

    unsigned lmax = 0u;
#pragma unroll
    for (int j = 0; j < 64; j++) lmax = (key[j] > lmax) ? key[j] : lmax;
    unsigned lo = __reduce_min_sync(0xFFFFFFFFu, lmax);
    unsigned hi = __reduce_max_sync(0xFFFFFFFFu, lmax);

#pragma unroll 1
    for (int it = 0; it < 32; ++it) {
        if (lo >= hi) break;
        unsigned span = hi - lo;
        unsigned mid = lo + (span >> 1) + (span & 1u);
        int c = 0;
#pragma unroll
        for (int j = 0; j < 64; j++) c += (key[j] >= mid) ? 1 : 0;
        c = __reduce_add_sync(0xFFFFFFFFu, c);
        if (c >= TOPK) lo = mid; else hi = mid - 1;
    }
    unsigned T = lo;

    int cg = 0;
#pragma unroll
    for (int j = 0; j < 64; j++) cg += (key[j] > T) ? 1 : 0;
    cg = __reduce_add_sync(0xFFFFFFFFu, cg);
    int rem = TOPK - cg;

    unsigned lmask = (1u << lane) - 1u;
    unsigned long long selmask = 0ull;
    unsigned kmin_in = 0xFFFFFFFFu;
    unsigned kmax_out = 0u;
#pragma unroll 1
    for (int j = 0; j < 64; j++) {
        unsigned k = key[j];
        bool eq = (k == T);
        unsigned em = __ballot_sync(0xFFFFFFFFu, eq);
        bool pick = eq && ((int)__popc(em & lmask) < rem);
        bool sel  = (k > T) || pick;
        if (sel) { selmask |= (1ull << j); if (k < kmin_in) kmin_in = k; }
        else     { if (k > kmax_out) kmax_out = k; }
        rem -= __popc(em);
        if (rem < 0) rem = 0;
    }
    kmin_in  = __reduce_min_sync(0xFFFFFFFFu, kmin_in);
    kmax_out = __reduce_max_sync(0xFFFFFFFFu, kmax_out);

    float vin  = key_decode(kmin_in);
    float vout = key_decode(kmax_out);

    if (vin - vout < AMBIG_W) {
        float wlo = vout - AMBIG_W;
        float whi = vin + AMBIG_W;
        int ncand = 0;
#pragma unroll 1
        for (int j = 0; j < 64; j++) {
            float v = key_decode(key[j]);
            bool isc = (v >= wlo) && (v <= whi);
            unsigned bal = __ballot_sync(0xFFFFFFFFu, isc);
            if (isc) {
                int pos = ncand + __popc(bal & lmask);
                if (pos < MAXCAND) {
                    s_cidx[warp][pos] = j * 32 + lane;
                    s_csel[warp][pos] = (int)((selmask >> j) & 1ull);
                }
            }
            ncand += __popc(bal);
        }
        if (ncand > MAXCAND) ncand = MAXCAND;
        __syncwarp();

        const float* xr = x + (size_t)row * DIN;
        for (int c = 0; c < ncand; c++) {
            const float* wr = Wenc + (size_t)s_cidx[warp][c] * DIN;
            double s = 0.0;
#pragma unroll
            for (int t = 0; t < DIN / 32; t++) {
                int kk = lane + t * 32;
                s += (double)xr[kk] * (double)wr[kk];
            }
#pragma unroll
            for (int off = 16; off > 0; off >>= 1)
                s += __shfl_down_sync(0xFFFFFFFFu, s, off);
            if (lane == 0) s_cval[warp][c] = s;
            __syncwarp();
        }

        if (lane == 0) {
            int nkeep = 0;
            for (int c = 0; c < ncand; c++) nkeep += s_csel[warp][c];
            unsigned chosen = 0;
            for (int s = 0; s < nkeep; s++) {
                int best = -1;
                for (int c = 0; c < ncand; c++) {
                    if (chosen & (1u << c)) continue;
                    if (best < 0 ||
                        s_cval[warp][c] > s_cval[warp][best] ||
                        (s_cval[warp][c] == s_cval[warp][best] &&
                         s_cidx[warp][c] < s_cidx[warp][best]))
                        best = c;
                }
                chosen |= (1u << best);
            }
            s_chosen[warp] = chosen;
        }
        __syncwarp();
        unsigned chosen = s_chosen[warp];

        for (int c = 0; c < ncand; c++) {
            int fi = s_cidx[warp][c];
            if ((fi & 31) == lane) {
                int j = fi >> 5;
                if (chosen & (1u << c)) selmask |=  (1ull << j);
                else                    selmask &= ~(1ull << j);
            }
        }
        __syncwarp();
    }

    float* orow = hsp + (size_t)row * DHID;
    int nsel = 0;
#pragma unroll 1
    for (int j = 0; j < 64; j++) {
        bool sel = (selmask >> j) & 1ull;
        unsigned k = key[j];
        float v = (k > 0x80000000u) ? __uint_as_float(k ^ 0x80000000u) : 0.0f;
        orow[j * 32 + lane] = sel ? v : 0.0f;

        unsigned sm2 = __ballot_sync(0xFFFFFFFFu, sel);
        if (sel) {
            int slot = nsel + __popc(sm2 & lmask);
            g_tidx[(size_t)row * TOPK + slot] = j * 32 + lane;
            g_tval[(size_t)row * TOPK + slot] = v;
        }
        nsel += __popc(sm2);
    }
}

// ============================================================
// Sparse decoder: recon[row,:] = b_dec + sum_k val_k * Wt[idx_k,:]
// ============================================================
__global__ __launch_bounds__(192)
void decode_kernel(const float* __restrict__ bdec, float* __restrict__ recon)
{
    int row = blockIdx.x;
    int t = threadIdx.x;
    __shared__ float sval[TOPK];
    __shared__ int   sidx[TOPK];
    if (t < TOPK) {
        sval[t] = g_tval[(size_t)row * TOPK + t];
        sidx[t] = g_tidx[(size_t)row * TOPK + t];
    }
    __syncthreads();

    float4 acc = *(const float4*)&bdec[t * 4];
#pragma unroll 8
    for (int k = 0; k < TOPK; k++) {
        float v = sval[k];
        float4 w = *(const float4*)&g_Wt[(size_t)sidx[k] * DIN + t * 4];
        acc.x += v * w.x; acc.y += v * w.y; acc.z += v * w.z; acc.w += v * w.w;
    }
    *(float4*)&recon[(size_t)row * DIN + t * 4] = acc;
}

// ============================================================
extern "C" void kernel_launch(void* const* d_in, const int* in_sizes, int n_in,
                              void* d_out, int out_size)
{
    const float* x     = (const float*)d_in[0];
    const float* W_enc = (const float*)d_in[1];
    const float* b_enc = (const float*)d_in[2];
    const float* W_dec = (const float*)d_in[3];
    const float* b_dec = (const float*)d_in[4];

    float* out   = (float*)d_out;
    float* recon = out;                                 // [B, 768]
    float* hsp   = out + (size_t)BATCH * DIN;           // [B, 2048]
    float* hpre  = hsp + (size_t)BATCH * DHID;          // [B, 2048]

    __half *ah, *bh, *bl;
    cudaGetSymbolAddress((void**)&ah, g_Ah);
    cudaGetSymbolAddress((void**)&bh, g_Bh);
    cudaGetSymbolAddress((void**)&bl, g_Bl);

    cudaFuncSetAttribute(gemm_fp16x2, cudaFuncAttributeMaxDynamicSharedMemorySize,
                         (int)GEMM_SMEM);

    round_x_kernel<<<(BATCH * DIN / 2) / 256, 256>>>(x, ah);
    split_w_kernel<<<(DHID * DIN / 2) / 256, 256>>>(W_enc, bh, bl);
    transpose_kernel<<<dim3(DHID / 32, DIN / 32), dim3(32, 8)>>>(W_dec);
    gemm_fp16x2<<<dim3(DHID / 128, BATCH / 128), 256, GEMM_SMEM>>>(b_enc, hpre);
    topk_kernel<<<BATCH / 8, 256>>>(hpre, hsp, x, W_enc);
    decode_kernel<<<BATCH, 192>>>(b_dec, recon);
}

// round 13
// speedup vs baseline: 1.4655x; 1.0748x over previous
#include <cuda_runtime.h>
#include <cuda_fp16.h>
#include <mma.h>
#include <cstdint>

using namespace nvcuda;

#define BATCH 32768
#define DIN   768
#define DHID  2048
#define TOPK  32

// -------- scratch (no cudaMalloc allowed) --------
__device__ __align__(16) float g_Wt[(size_t)DHID * DIN];   // W_dec^T [2048][768]
__device__ int   g_tidx[(size_t)BATCH * TOPK];
__device__ float g_tval[(size_t)BATCH * TOPK];
__device__ __align__(16) __half g_Ah[(size_t)BATCH * DIN];  // x rounded to fp16
__device__ __align__(16) __half g_Bh[(size_t)DHID * DIN];   // W_enc hi (fp16)
__device__ __align__(16) __half g_Bl[(size_t)DHID * DIN];   // W_enc lo (fp16)

// ============================================================
// x -> fp16 round
// ============================================================
__global__ __launch_bounds__(256)
void round_x_kernel(const float* __restrict__ src, __half* __restrict__ dst)
{
    int i = blockIdx.x * 256 + threadIdx.x;
    float2 v = ((const float2*)src)[i];
    ((__half2*)dst)[i] = __floats2half2_rn(v.x, v.y);
}

// ============================================================
// W_enc -> (hi, lo) fp16 split
// ============================================================
__global__ __launch_bounds__(256)
void split_w_kernel(const float* __restrict__ src,
                    __half* __restrict__ hi, __half* __restrict__ lo)
{
    int i = blockIdx.x * 256 + threadIdx.x;
    float2 v = ((const float2*)src)[i];
    __half h0 = __float2half_rn(v.x);
    __half h1 = __float2half_rn(v.y);
    __half l0 = __float2half_rn(v.x - __half2float(h0));
    __half l1 = __float2half_rn(v.y - __half2float(h1));
    ((__half2*)hi)[i] = __halves2half2(h0, h1);
    ((__half2*)lo)[i] = __halves2half2(l0, l1);
}

// ============================================================
// W_dec [768][2048] -> g_Wt [2048][768]
// ============================================================
__global__ void transpose_kernel(const float* __restrict__ W)
{
    __shared__ float tile[32][33];
    int bx = blockIdx.x * 32, by = blockIdx.y * 32;
    int tx = threadIdx.x, ty = threadIdx.y;
#pragma unroll
    for (int i = 0; i < 32; i += 8)
        tile[ty + i][tx] = W[(size_t)(by + ty + i) * DHID + bx + tx];
    __syncthreads();
#pragma unroll
    for (int i = 0; i < 32; i += 8)
        g_Wt[(size_t)(bx + ty + i) * DIN + by + tx] = tile[tx][ty + i];
}

// ============================================================
// Encoder GEMM (R12 config, best measured): fp16 2-term,
// cp.async 2-stage, 2 CTAs/SM, block 128x128, warp tile 64x32.
// ============================================================
#define BK     32
#define HS     40                       // halves per row (32 + 8 pad)
#define PART   (128 * HS)
#define STG_H  (3 * PART)
#define NKT    (DIN / BK)               // 24
#define GEMM_SMEM (2 * STG_H * sizeof(__half))   // 61440 B

__device__ __forceinline__ void cp16(__half* dst, const __half* src)
{
    unsigned d = (unsigned)__cvta_generic_to_shared(dst);
    asm volatile("cp.async.cg.shared.global [%0], [%1], 16;\n" :: "r"(d), "l"(src));
}

__global__ __launch_bounds__(256, 2)
void gemm_fp16x2(const float* __restrict__ bias, float* __restrict__ C)
{
    extern __shared__ __half smh[];

    int tid  = threadIdx.x;
    int warp = tid >> 5;
    int wm   = warp & 1;
    int wn   = warp >> 1;
    int m0 = blockIdx.y * 128;
    int n0 = blockIdx.x * 128;

    using FragA = wmma::fragment<wmma::matrix_a, 16, 16, 16, __half, wmma::row_major>;
    using FragB = wmma::fragment<wmma::matrix_b, 16, 16, 16, __half, wmma::col_major>;
    using FragC = wmma::fragment<wmma::accumulator, 16, 16, 16, float>;

    float* bsm = (float*)smh;
    for (int i = tid; i < 16 * 128; i += 256)
        bsm[i] = bias[n0 + (i & 127)];
    __syncthreads();

    FragC acc[4][2];
#pragma unroll
    for (int i = 0; i < 4; i++)
#pragma unroll
        for (int j = 0; j < 2; j++)
            wmma::load_matrix_sync(acc[i][j], &bsm[wn * 32 + j * 16], 128, wmma::mem_row_major);
    __syncthreads();

    auto load_tile = [&](int buf, int kt) {
        __half* s = smh + buf * STG_H;
        int k0 = kt * BK;
#pragma unroll
        for (int p = 0; p < 2; p++) {
            int f  = tid + p * 256;
            int r  = f >> 2;
            int ch = (f & 3) * 8;
            size_t ga = (size_t)(m0 + r) * DIN + k0 + ch;
            size_t gb = (size_t)(n0 + r) * DIN + k0 + ch;
            cp16(&s[0 * PART + r * HS + ch], &g_Ah[ga]);
            cp16(&s[1 * PART + r * HS + ch], &g_Bh[gb]);
            cp16(&s[2 * PART + r * HS + ch], &g_Bl[gb]);
        }
        asm volatile("cp.async.commit_group;\n" ::);
    };

    load_tile(0, 0);

    for (int t = 0; t < NKT; t++) {
        if (t + 1 < NKT) load_tile((t + 1) & 1, t + 1);
        else             asm volatile("cp.async.commit_group;\n" ::);

        asm volatile("cp.async.wait_group 1;\n" ::);
        __syncthreads();

        __half* s  = smh + (t & 1) * STG_H;
        __half* Ah = s;
        __half* Bh = s + PART;
        __half* Bl = s + 2 * PART;

#pragma unroll
        for (int ks = 0; ks < BK; ks += 16) {
            FragB bh[2], bl[2];
#pragma unroll
            for (int j = 0; j < 2; j++) {
                wmma::load_matrix_sync(bh[j], &Bh[(wn * 32 + j * 16) * HS + ks], HS);
                wmma::load_matrix_sync(bl[j], &Bl[(wn * 32 + j * 16) * HS + ks], HS);
            }
#pragma unroll
            for (int i = 0; i < 4; i++) {
                FragA ah;
                wmma::load_matrix_sync(ah, &Ah[(wm * 64 + i * 16) * HS + ks], HS);
#pragma unroll
                for (int j = 0; j < 2; j++)
                    wmma::mma_sync(acc[i][j], ah, bh[j], acc[i][j]);
#pragma unroll
                for (int j = 0; j < 2; j++)
                    wmma::mma_sync(acc[i][j], ah, bl[j], acc[i][j]);
            }
        }
        __syncthreads();
    }

#pragma unroll
    for (int i = 0; i < 4; i++)
#pragma unroll
        for (int j = 0; j < 2; j++) {
            float* cp = &C[(size_t)(m0 + wm * 64 + i * 16) * DHID + n0 + wn * 32 + j * 16];
            wmma::store_matrix_sync(cp, acc[i][j], DHID, wmma::mem_row_major);
        }
}

// ============================================================
// Top-K v3: candidate-compressed bisection.
//  1) lo = min lane-max (provable threshold lower bound)
//  2) full-width bisection only until count(>=lo) <= 128
//  3) compress candidates to smem; fine bisection over 4 regs/lane
//  4) exact fp64 re-rank of the ambiguous boundary (unchanged)
// Element layout: val[4g+c] = column g*128 + lane*4 + c.
// ============================================================
#define AMBIG_W 1e-3f
#define MAXCAND 16

__device__ __forceinline__ unsigned fmono(float f)
{
    unsigned u = __float_as_uint(f);
    return (u & 0x80000000u) ? ~u : (u | 0x80000000u);
}
__device__ __forceinline__ float key_decode(unsigned k)
{
    return (k >= 0x80000000u) ? __uint_as_float(k ^ 0x80000000u)
                              : __uint_as_float(~k);
}

__global__ __launch_bounds__(256, 2)
void topk_kernel(const float* __restrict__ hpre, float* __restrict__ hsp,
                 const float* __restrict__ x, const float* __restrict__ Wenc)
{
    const unsigned FULL = 0xFFFFFFFFu;
    int lane = threadIdx.x & 31;
    int warp = threadIdx.x >> 5;
    int row  = blockIdx.x * 8 + warp;
    const float4* p4 = (const float4*)(hpre + (size_t)row * DHID);
    unsigned lmask = (1u << lane) - 1u;

    __shared__ float  s_cv[8][128];
    __shared__ int    s_cidx[8][MAXCAND];
    __shared__ double s_cval[8][MAXCAND];
    __shared__ int    s_csel[8][MAXCAND];
    __shared__ unsigned s_chosen[8];

    // ---- load 64 values per lane (16 x float4) ----
    float val[64];
    float vmax = -3.0e38f;
#pragma unroll
    for (int g = 0; g < 16; g++) {
        float4 v = p4[g * 32 + lane];
        val[4*g+0] = v.x; val[4*g+1] = v.y; val[4*g+2] = v.z; val[4*g+3] = v.w;
        vmax = fmaxf(vmax, fmaxf(fmaxf(v.x, v.y), fmaxf(v.z, v.w)));
    }

    unsigned lo = __reduce_min_sync(FULL, fmono(vmax));
    unsigned hi = __reduce_max_sync(FULL, fmono(vmax));
    float loF = key_decode(lo);

    // ---- coarse full-width refinement until <=128 candidates ----
    int c_lo;
    {
        int c = 0;
#pragma unroll
        for (int j = 0; j < 64; j++) c += (val[j] >= loF) ? 1 : 0;
        c_lo = __reduce_add_sync(FULL, c);
    }
#pragma unroll 1
    for (int it = 0; it < 32 && c_lo > 128 && lo < hi; ++it) {
        unsigned span = hi - lo;
        unsigned mid = lo + (span >> 1) + (span & 1u);
        float mf = key_decode(mid);
        int c = 0;
#pragma unroll
        for (int j = 0; j < 64; j++) c += (val[j] >= mf) ? 1 : 0;
        c = __reduce_add_sync(FULL, c);
        if (c >= TOPK) { lo = mid; loF = mf; c_lo = c; }
        else            hi = mid - 1;
    }

    // ---- compress candidates (val >= loF) into smem ----
    int cnt = 0;
#pragma unroll
    for (int j = 0; j < 64; j++) cnt += (val[j] >= loF) ? 1 : 0;
    int off = cnt;
#pragma unroll
    for (int d = 1; d < 32; d <<= 1) {
        int n = __shfl_up_sync(FULL, off, d);
        if (lane >= d) off += n;
    }
    int ncand = __shfl_sync(FULL, off, 31);
    off -= cnt;
    {
        int o = off;
#pragma unroll
        for (int j = 0; j < 64; j++) {
            if (val[j] >= loF) {
                if (o < 128) s_cv[warp][o] = val[j];
                o++;
            }
        }
    }
    if (ncand > 128) ncand = 128;
    __syncwarp();

    float cv[4];
#pragma unroll
    for (int r = 0; r < 4; r++) {
        int pos = lane + r * 32;
        cv[r] = (pos < ncand) ? s_cv[warp][pos] : -3.0e38f;
    }

    // ---- fine bisection over candidate registers ----
#pragma unroll 1
    for (int it = 0; it < 32; ++it) {
        if (lo >= hi) break;
        unsigned span = hi - lo;
        unsigned mid = lo + (span >> 1) + (span & 1u);
        float mf = key_decode(mid);
        int c = 0;
#pragma unroll
        for (int r = 0; r < 4; r++) c += (cv[r] >= mf) ? 1 : 0;
        c = __reduce_add_sync(FULL, c);
        if (c >= TOPK) lo = mid; else hi = mid - 1;
    }
    float Tf = key_decode(lo);

    int cg = 0;
#pragma unroll
    for (int r = 0; r < 4; r++) cg += (cv[r] > Tf) ? 1 : 0;
    cg = __reduce_add_sync(FULL, cg);
    int rem = TOPK - cg;

    // ---- build selection mask; ties picked warp-ordered (rescue
    //      re-ranks the boundary exactly, so tie ORDER is safe) ----
    unsigned long long selmask = 0ull, tiemask = 0ull;
    float vin_l = 3.0e38f, vout_l = -3.0e38f;
#pragma unroll
    for (int j = 0; j < 64; j++) {
        float v = val[j];
        if (v > Tf)       { selmask |= 1ull << j; vin_l = fminf(vin_l, v); }
        else if (v == Tf) { tiemask |= 1ull << j; }
        else              { vout_l = fmaxf(vout_l, v); }
    }
    int tcnt = __popcll(tiemask);
    int toff = tcnt;
#pragma unroll
    for (int d = 1; d < 32; d <<= 1) {
        int n = __shfl_up_sync(FULL, toff, d);
        if (lane >= d) toff += n;
    }
    toff -= tcnt;
    {
        int r = toff;
#pragma unroll
        for (int j = 0; j < 64; j++) {
            if ((tiemask >> j) & 1ull) {
                if (r < rem) { selmask |= 1ull << j; vin_l = fminf(vin_l, val[j]); }
                else         { vout_l = fmaxf(vout_l, val[j]); }
                r++;
            }
        }
    }

    unsigned vi = __reduce_min_sync(FULL, fmono(vin_l));
    unsigned vo = __reduce_max_sync(FULL, fmono(vout_l));
    float vin  = key_decode(vi);
    float vout = key_decode(vo);

    // ---- fp64 rescue of ambiguous boundary ----
    if (vin - vout < AMBIG_W) {
        float wlo = vout - AMBIG_W;
        float whi = vin + AMBIG_W;
        int ncw = 0;
#pragma unroll 1
        for (int j = 0; j < 64; j++) {
            float v = val[j];
            bool isc = (v >= wlo) && (v <= whi);
            unsigned bal = __ballot_sync(FULL, isc);
            if (isc) {
                int pos = ncw + __popc(bal & lmask);
                if (pos < MAXCAND) {
                    s_cidx[warp][pos] = (j >> 2) * 128 + lane * 4 + (j & 3);
                    s_csel[warp][pos] = (int)((selmask >> j) & 1ull);
                }
            }
            ncw += __popc(bal);
        }
        if (ncw > MAXCAND) ncw = MAXCAND;
        __syncwarp();

        const float* xr = x + (size_t)row * DIN;
        for (int c = 0; c < ncw; c++) {
            const float* wr = Wenc + (size_t)s_cidx[warp][c] * DIN;
            double s = 0.0;
#pragma unroll
            for (int t = 0; t < DIN / 32; t++) {
                int kk = lane + t * 32;
                s += (double)xr[kk] * (double)wr[kk];
            }
#pragma unroll
            for (int o2 = 16; o2 > 0; o2 >>= 1)
                s += __shfl_down_sync(FULL, s, o2);
            if (lane == 0) s_cval[warp][c] = s;
            __syncwarp();
        }

        if (lane == 0) {
            int nkeep = 0;
            for (int c = 0; c < ncw; c++) nkeep += s_csel[warp][c];
            unsigned chosen = 0;
            for (int s = 0; s < nkeep; s++) {
                int best = -1;
                for (int c = 0; c < ncw; c++) {
                    if (chosen & (1u << c)) continue;
                    if (best < 0 ||
                        s_cval[warp][c] > s_cval[warp][best] ||
                        (s_cval[warp][c] == s_cval[warp][best] &&
                         s_cidx[warp][c] < s_cidx[warp][best]))
                        best = c;
                }
                chosen |= (1u << best);
            }
            s_chosen[warp] = chosen;
        }
        __syncwarp();
        unsigned chosen = s_chosen[warp];

        for (int c = 0; c < ncw; c++) {
            int fi = s_cidx[warp][c];
            if (((fi >> 2) & 31) == lane) {
                int j = ((fi >> 7) << 2) | (fi & 3);
                if (chosen & (1u << c)) selmask |=  (1ull << j);
                else                    selmask &= ~(1ull << j);
            }
        }
        __syncwarp();
    }

    // ---- dense write (float4) ----
    float4* orow4 = (float4*)(hsp + (size_t)row * DHID);
#pragma unroll
    for (int g = 0; g < 16; g++) {
        float4 o;
        o.x = ((selmask >> (4*g+0)) & 1ull) ? fmaxf(val[4*g+0], 0.0f) : 0.0f;
        o.y = ((selmask >> (4*g+1)) & 1ull) ? fmaxf(val[4*g+1], 0.0f) : 0.0f;
        o.z = ((selmask >> (4*g+2)) & 1ull) ? fmaxf(val[4*g+2], 0.0f) : 0.0f;
        o.w = ((selmask >> (4*g+3)) & 1ull) ? fmaxf(val[4*g+3], 0.0f) : 0.0f;
        orow4[g * 32 + lane] = o;
    }

    // ---- compact list via per-lane scan (order irrelevant) ----
    int scnt = __popcll(selmask);
    int soff = scnt;
#pragma unroll
    for (int d = 1; d < 32; d <<= 1) {
        int n = __shfl_up_sync(FULL, soff, d);
        if (lane >= d) soff += n;
    }
    int nsel_tot = __shfl_sync(FULL, soff, 31);
    soff -= scnt;
    {
        int so = soff;
#pragma unroll
        for (int j = 0; j < 64; j++) {
            if ((selmask >> j) & 1ull) {
                if (so < TOPK) {
                    g_tidx[(size_t)row * TOPK + so] = (j >> 2) * 128 + lane * 4 + (j & 3);
                    g_tval[(size_t)row * TOPK + so] = fmaxf(val[j], 0.0f);
                }
                so++;
            }
        }
    }
    if (nsel_tot < TOPK && lane == 0) {
        for (int s = nsel_tot; s < TOPK; s++) {
            g_tidx[(size_t)row * TOPK + s] = 0;
            g_tval[(size_t)row * TOPK + s] = 0.0f;
        }
    }
}

// ============================================================
// Sparse decoder: recon[row,:] = b_dec + sum_k val_k * Wt[idx_k,:]
// ============================================================
__global__ __launch_bounds__(192)
void decode_kernel(const float* __restrict__ bdec, float* __restrict__ recon)
{
    int row = blockIdx.x;
    int t = threadIdx.x;
    __shared__ float sval[TOPK];
    __shared__ int   sidx[TOPK];
    if (t < TOPK) {
        sval[t] = g_tval[(size_t)row * TOPK + t];
        sidx[t] = g_tidx[(size_t)row * TOPK + t];
    }
    __syncthreads();

    float4 acc = *(const float4*)&bdec[t * 4];
#pragma unroll 8
    for (int k = 0; k < TOPK; k++) {
        float v = sval[k];
        float4 w = *(const float4*)&g_Wt[(size_t)sidx[k] * DIN + t * 4];
        acc.x += v * w.x; acc.y += v * w.y; acc.z += v * w.z; acc.w += v * w.w;
    }
    *(float4*)&recon[(size_t)row * DIN + t * 4] = acc;
}

// ============================================================
extern "C" void kernel_launch(void* const* d_in, const int* in_sizes, int n_in,
                              void* d_out, int out_size)
{
    const float* x     = (const float*)d_in[0];
    const float* W_enc = (const float*)d_in[1];
    const float* b_enc = (const float*)d_in[2];
    const float* W_dec = (const float*)d_in[3];
    const float* b_dec = (const float*)d_in[4];

    float* out   = (float*)d_out;
    float* recon = out;                                 // [B, 768]
    float* hsp   = out + (size_t)BATCH * DIN;           // [B, 2048]
    float* hpre  = hsp + (size_t)BATCH * DHID;          // [B, 2048]

    __half *ah, *bh, *bl;
    cudaGetSymbolAddress((void**)&ah, g_Ah);
    cudaGetSymbolAddress((void**)&bh, g_Bh);
    cudaGetSymbolAddress((void**)&bl, g_Bl);

    cudaFuncSetAttribute(gemm_fp16x2, cudaFuncAttributeMaxDynamicSharedMemorySize,
                         (int)GEMM_SMEM);

    round_x_kernel<<<(BATCH * DIN / 2) / 256, 256>>>(x, ah);
    split_w_kernel<<<(DHID * DIN / 2) / 256, 256>>>(W_enc, bh, bl);
    transpose_kernel<<<dim3(DHID / 32, DIN / 32), dim3(32, 8)>>>(W_dec);
    gemm_fp16x2<<<dim3(DHID / 128, BATCH / 128), 256, GEMM_SMEM>>>(b_enc, hpre);
    topk_kernel<<<BATCH / 8, 256>>>(hpre, hsp, x, W_enc);
    decode_kernel<<<BATCH, 192>>>(b_dec, recon);
}

// round 14
// speedup vs baseline: 1.8210x; 1.2425x over previous
#include <cuda_runtime.h>
#include <cuda_fp16.h>
#include <mma.h>
#include <cstdint>

using namespace nvcuda;

#define BATCH 32768
#define DIN   768
#define DHID  2048
#define TOPK  32

// -------- scratch (no cudaMalloc allowed) --------
__device__ __align__(16) float g_Wt[(size_t)DHID * DIN];   // W_dec^T [2048][768]
__device__ int   g_tidx[(size_t)BATCH * TOPK];
__device__ float g_tval[(size_t)BATCH * TOPK];
__device__ __align__(16) __half g_Ah[(size_t)BATCH * DIN];  // x rounded to fp16
__device__ __align__(16) __half g_Bh[(size_t)DHID * DIN];   // W_enc rounded to fp16

// ============================================================
// f32 -> fp16 round (used for both x and W_enc)
// ============================================================
__global__ __launch_bounds__(256)
void round_x_kernel(const float* __restrict__ src, __half* __restrict__ dst)
{
    int i = blockIdx.x * 256 + threadIdx.x;
    float2 v = ((const float2*)src)[i];
    ((__half2*)dst)[i] = __floats2half2_rn(v.x, v.y);
}

// ============================================================
// W_dec [768][2048] -> g_Wt [2048][768]
// ============================================================
__global__ void transpose_kernel(const float* __restrict__ W)
{
    __shared__ float tile[32][33];
    int bx = blockIdx.x * 32, by = blockIdx.y * 32;
    int tx = threadIdx.x, ty = threadIdx.y;
#pragma unroll
    for (int i = 0; i < 32; i += 8)
        tile[ty + i][tx] = W[(size_t)(by + ty + i) * DHID + bx + tx];
    __syncthreads();
#pragma unroll
    for (int i = 0; i < 32; i += 8)
        g_Wt[(size_t)(bx + ty + i) * DIN + by + tx] = tile[tx][ty + i];
}

// ============================================================
// Encoder GEMM, pure fp16 (1 term), cp.async 2-stage, 2 CTAs/SM.
// Block 128x128, BK=32, 8 warps (Wm=2,Wn=4), warp tile 64x32.
// Stage: Ah|Bh, 128 x 40 halves each.
// ============================================================
#define BK     32
#define HS     40                       // halves per row (32 + 8 pad)
#define PART   (128 * HS)
#define STG_H  (2 * PART)
#define NKT    (DIN / BK)               // 24
#define GEMM_SMEM (2 * STG_H * sizeof(__half))   // 40960 B

__device__ __forceinline__ void cp16(__half* dst, const __half* src)
{
    unsigned d = (unsigned)__cvta_generic_to_shared(dst);
    asm volatile("cp.async.cg.shared.global [%0], [%1], 16;\n" :: "r"(d), "l"(src));
}

__global__ __launch_bounds__(256, 2)
void gemm_fp16(const float* __restrict__ bias, float* __restrict__ C)
{
    extern __shared__ __half smh[];

    int tid  = threadIdx.x;
    int warp = tid >> 5;
    int wm   = warp & 1;
    int wn   = warp >> 1;
    int m0 = blockIdx.y * 128;
    int n0 = blockIdx.x * 128;

    using FragA = wmma::fragment<wmma::matrix_a, 16, 16, 16, __half, wmma::row_major>;
    using FragB = wmma::fragment<wmma::matrix_b, 16, 16, 16, __half, wmma::col_major>;
    using FragC = wmma::fragment<wmma::accumulator, 16, 16, 16, float>;

    float* bsm = (float*)smh;
    for (int i = tid; i < 16 * 128; i += 256)
        bsm[i] = bias[n0 + (i & 127)];
    __syncthreads();

    FragC acc[4][2];
#pragma unroll
    for (int i = 0; i < 4; i++)
#pragma unroll
        for (int j = 0; j < 2; j++)
            wmma::load_matrix_sync(acc[i][j], &bsm[wn * 32 + j * 16], 128, wmma::mem_row_major);
    __syncthreads();

    auto load_tile = [&](int buf, int kt) {
        __half* s = smh + buf * STG_H;
        int k0 = kt * BK;
#pragma unroll
        for (int p = 0; p < 2; p++) {
            int f  = tid + p * 256;
            int r  = f >> 2;
            int ch = (f & 3) * 8;
            size_t ga = (size_t)(m0 + r) * DIN + k0 + ch;
            size_t gb = (size_t)(n0 + r) * DIN + k0 + ch;
            cp16(&s[0 * PART + r * HS + ch], &g_Ah[ga]);
            cp16(&s[1 * PART + r * HS + ch], &g_Bh[gb]);
        }
        asm volatile("cp.async.commit_group;\n" ::);
    };

    load_tile(0, 0);

    for (int t = 0; t < NKT; t++) {
        if (t + 1 < NKT) load_tile((t + 1) & 1, t + 1);
        else             asm volatile("cp.async.commit_group;\n" ::);

        asm volatile("cp.async.wait_group 1;\n" ::);
        __syncthreads();

        __half* s  = smh + (t & 1) * STG_H;
        __half* Ah = s;
        __half* Bh = s + PART;

#pragma unroll
        for (int ks = 0; ks < BK; ks += 16) {
            FragB bh[2];
#pragma unroll
            for (int j = 0; j < 2; j++)
                wmma::load_matrix_sync(bh[j], &Bh[(wn * 32 + j * 16) * HS + ks], HS);
#pragma unroll
            for (int i = 0; i < 4; i++) {
                FragA ah;
                wmma::load_matrix_sync(ah, &Ah[(wm * 64 + i * 16) * HS + ks], HS);
#pragma unroll
                for (int j = 0; j < 2; j++)
                    wmma::mma_sync(acc[i][j], ah, bh[j], acc[i][j]);
            }
        }
        __syncthreads();
    }

#pragma unroll
    for (int i = 0; i < 4; i++)
#pragma unroll
        for (int j = 0; j < 2; j++) {
            float* cp = &C[(size_t)(m0 + wm * 64 + i * 16) * DHID + n0 + wn * 32 + j * 16];
            wmma::store_matrix_sync(cp, acc[i][j], DHID, wmma::mem_row_major);
        }
}

// ============================================================
// Top-K v3 (R13 best): candidate-compressed bisection + exact
// fp64 re-rank of the ambiguous boundary. Window widened to
// cover 1-term fp16 GEMM noise (6 sigma).
// Element layout: val[4g+c] = column g*128 + lane*4 + c.
// ============================================================
#define AMBIG_W 1.5e-3f
#define MAXCAND 16

__device__ __forceinline__ unsigned fmono(float f)
{
    unsigned u = __float_as_uint(f);
    return (u & 0x80000000u) ? ~u : (u | 0x80000000u);
}
__device__ __forceinline__ float key_decode(unsigned k)
{
    return (k >= 0x80000000u) ? __uint_as_float(k ^ 0x80000000u)
                              : __uint_as_float(~k);
}

__global__ __launch_bounds__(256, 2)
void topk_kernel(const float* __restrict__ hpre, float* __restrict__ hsp,
                 const float* __restrict__ x, const float* __restrict__ Wenc)
{
    const unsigned FULL = 0xFFFFFFFFu;
    int lane = threadIdx.x & 31;
    int warp = threadIdx.x >> 5;
    int row  = blockIdx.x * 8 + warp;
    const float4* p4 = (const float4*)(hpre + (size_t)row * DHID);
    unsigned lmask = (1u << lane) - 1u;

    __shared__ float  s_cv[8][128];
    __shared__ int    s_cidx[8][MAXCAND];
    __shared__ double s_cval[8][MAXCAND];
    __shared__ int    s_csel[8][MAXCAND];
    __shared__ unsigned s_chosen[8];

    float val[64];
    float vmax = -3.0e38f;
#pragma unroll
    for (int g = 0; g < 16; g++) {
        float4 v = p4[g * 32 + lane];
        val[4*g+0] = v.x; val[4*g+1] = v.y; val[4*g+2] = v.z; val[4*g+3] = v.w;
        vmax = fmaxf(vmax, fmaxf(fmaxf(v.x, v.y), fmaxf(v.z, v.w)));
    }

    unsigned lo = __reduce_min_sync(FULL, fmono(vmax));
    unsigned hi = __reduce_max_sync(FULL, fmono(vmax));
    float loF = key_decode(lo);

    int c_lo;
    {
        int c = 0;
#pragma unroll
        for (int j = 0; j < 64; j++) c += (val[j] >= loF) ? 1 : 0;
        c_lo = __reduce_add_sync(FULL, c);
    }
#pragma unroll 1
    for (int it = 0; it < 32 && c_lo > 128 && lo < hi; ++it) {
        unsigned span = hi - lo;
        unsigned mid = lo + (span >> 1) + (span & 1u);
        float mf = key_decode(mid);
        int c = 0;
#pragma unroll
        for (int j = 0; j < 64; j++) c += (val[j] >= mf) ? 1 : 0;
        c = __reduce_add_sync(FULL, c);
        if (c >= TOPK) { lo = mid; loF = mf; c_lo = c; }
        else            hi = mid - 1;
    }

    int cnt = 0;
#pragma unroll
    for (int j = 0; j < 64; j++) cnt += (val[j] >= loF) ? 1 : 0;
    int off = cnt;
#pragma unroll
    for (int d = 1; d < 32; d <<= 1) {
        int n = __shfl_up_sync(FULL, off, d);
        if (lane >= d) off += n;
    }
    int ncand = __shfl_sync(FULL, off, 31);
    off -= cnt;
    {
        int o = off;
#pragma unroll
        for (int j = 0; j < 64; j++) {
            if (val[j] >= loF) {
                if (o < 128) s_cv[warp][o] = val[j];
                o++;
            }
        }
    }
    if (ncand > 128) ncand = 128;
    __syncwarp();

    float cv[4];
#pragma unroll
    for (int r = 0; r < 4; r++) {
        int pos = lane + r * 32;
        cv[r] = (pos < ncand) ? s_cv[warp][pos] : -3.0e38f;
    }

#pragma unroll 1
    for (int it = 0; it < 32; ++it) {
        if (lo >= hi) break;
        unsigned span = hi - lo;
        unsigned mid = lo + (span >> 1) + (span & 1u);
        float mf = key_decode(mid);
        int c = 0;
#pragma unroll
        for (int r = 0; r < 4; r++) c += (cv[r] >= mf) ? 1 : 0;
        c = __reduce_add_sync(FULL, c);
        if (c >= TOPK) lo = mid; else hi = mid - 1;
    }
    float Tf = key_decode(lo);

    int cg = 0;
#pragma unroll
    for (int r = 0; r < 4; r++) cg += (cv[r] > Tf) ? 1 : 0;
    cg = __reduce_add_sync(FULL, cg);
    int rem = TOPK - cg;

    unsigned long long selmask = 0ull, tiemask = 0ull;
    float vin_l = 3.0e38f, vout_l = -3.0e38f;
#pragma unroll
    for (int j = 0; j < 64; j++) {
        float v = val[j];
        if (v > Tf)       { selmask |= 1ull << j; vin_l = fminf(vin_l, v); }
        else if (v == Tf) { tiemask |= 1ull << j; }
        else              { vout_l = fmaxf(vout_l, v); }
    }
    int tcnt = __popcll(tiemask);
    int toff = tcnt;
#pragma unroll
    for (int d = 1; d < 32; d <<= 1) {
        int n = __shfl_up_sync(FULL, toff, d);
        if (lane >= d) toff += n;
    }
    toff -= tcnt;
    {
        int r = toff;
#pragma unroll
        for (int j = 0; j < 64; j++) {
            if ((tiemask >> j) & 1ull) {
                if (r < rem) { selmask |= 1ull << j; vin_l = fminf(vin_l, val[j]); }
                else         { vout_l = fmaxf(vout_l, val[j]); }
                r++;
            }
        }
    }

    unsigned vi = __reduce_min_sync(FULL, fmono(vin_l));
    unsigned vo = __reduce_max_sync(FULL, fmono(vout_l));
    float vin  = key_decode(vi);
    float vout = key_decode(vo);

    if (vin - vout < AMBIG_W) {
        float wlo = vout - AMBIG_W;
        float whi = vin + AMBIG_W;
        int ncw = 0;
#pragma unroll 1
        for (int j = 0; j < 64; j++) {
            float v = val[j];
            bool isc = (v >= wlo) && (v <= whi);
            unsigned bal = __ballot_sync(FULL, isc);
            if (isc) {
                int pos = ncw + __popc(bal & lmask);
                if (pos < MAXCAND) {
                    s_cidx[warp][pos] = (j >> 2) * 128 + lane * 4 + (j & 3);
                    s_csel[warp][pos] = (int)((selmask >> j) & 1ull);
                }
            }
            ncw += __popc(bal);
        }
        if (ncw > MAXCAND) ncw = MAXCAND;
        __syncwarp();

        const float* xr = x + (size_t)row * DIN;
        for (int c = 0; c < ncw; c++) {
            const float* wr = Wenc + (size_t)s_cidx[warp][c] * DIN;
            double s = 0.0;
#pragma unroll
            for (int t = 0; t < DIN / 32; t++) {
                int kk = lane + t * 32;
                s += (double)xr[kk] * (double)wr[kk];
            }
#pragma unroll
            for (int o2 = 16; o2 > 0; o2 >>= 1)
                s += __shfl_down_sync(FULL, s, o2);
            if (lane == 0) s_cval[warp][c] = s;
            __syncwarp();
        }

        if (lane == 0) {
            int nkeep = 0;
            for (int c = 0; c < ncw; c++) nkeep += s_csel[warp][c];
            unsigned chosen = 0;
            for (int s = 0; s < nkeep; s++) {
                int best = -1;
                for (int c = 0; c < ncw; c++) {
                    if (chosen & (1u << c)) continue;
                    if (best < 0 ||
                        s_cval[warp][c] > s_cval[warp][best] ||
                        (s_cval[warp][c] == s_cval[warp][best] &&
                         s_cidx[warp][c] < s_cidx[warp][best]))
                        best = c;
                }
                chosen |= (1u << best);
            }
            s_chosen[warp] = chosen;
        }
        __syncwarp();
        unsigned chosen = s_chosen[warp];

        for (int c = 0; c < ncw; c++) {
            int fi = s_cidx[warp][c];
            if (((fi >> 2) & 31) == lane) {
                int j = ((fi >> 7) << 2) | (fi & 3);
                if (chosen & (1u << c)) selmask |=  (1ull << j);
                else                    selmask &= ~(1ull << j);
            }
        }
        __syncwarp();
    }

    float4* orow4 = (float4*)(hsp + (size_t)row * DHID);
#pragma unroll
    for (int g = 0; g < 16; g++) {
        float4 o;
        o.x = ((selmask >> (4*g+0)) & 1ull) ? fmaxf(val[4*g+0], 0.0f) : 0.0f;
        o.y = ((selmask >> (4*g+1)) & 1ull) ? fmaxf(val[4*g+1], 0.0f) : 0.0f;
        o.z = ((selmask >> (4*g+2)) & 1ull) ? fmaxf(val[4*g+2], 0.0f) : 0.0f;
        o.w = ((selmask >> (4*g+3)) & 1ull) ? fmaxf(val[4*g+3], 0.0f) : 0.0f;
        orow4[g * 32 + lane] = o;
    }

    int scnt = __popcll(selmask);
    int soff = scnt;
#pragma unroll
    for (int d = 1; d < 32; d <<= 1) {
        int n = __shfl_up_sync(FULL, soff, d);
        if (lane >= d) soff += n;
    }
    int nsel_tot = __shfl_sync(FULL, soff, 31);
    soff -= scnt;
    {
        int so = soff;
#pragma unroll
        for (int j = 0; j < 64; j++) {
            if ((selmask >> j) & 1ull) {
                if (so < TOPK) {
                    g_tidx[(size_t)row * TOPK + so] = (j >> 2) * 128 + lane * 4 + (j & 3);
                    g_tval[(size_t)row * TOPK + so] = fmaxf(val[j], 0.0f);
                }
                so++;
            }
        }
    }
    if (nsel_tot < TOPK && lane == 0) {
        for (int s = nsel_tot; s < TOPK; s++) {
            g_tidx[(size_t)row * TOPK + s] = 0;
            g_tval[(size_t)row * TOPK + s] = 0.0f;
        }
    }
}

// ============================================================
// Sparse decoder: recon[row,:] = b_dec + sum_k val_k * Wt[idx_k,:]
// ============================================================
__global__ __launch_bounds__(192)
void decode_kernel(const float* __restrict__ bdec, float* __restrict__ recon)
{
    int row = blockIdx.x;
    int t = threadIdx.x;
    __shared__ float sval[TOPK];
    __shared__ int   sidx[TOPK];
    if (t < TOPK) {
        sval[t] = g_tval[(size_t)row * TOPK + t];
        sidx[t] = g_tidx[(size_t)row * TOPK + t];
    }
    __syncthreads();

    float4 acc = *(const float4*)&bdec[t * 4];
#pragma unroll 8
    for (int k = 0; k < TOPK; k++) {
        float v = sval[k];
        float4 w = *(const float4*)&g_Wt[(size_t)sidx[k] * DIN + t * 4];
        acc.x += v * w.x; acc.y += v * w.y; acc.z += v * w.z; acc.w += v * w.w;
    }
    *(float4*)&recon[(size_t)row * DIN + t * 4] = acc;
}

// ============================================================
extern "C" void kernel_launch(void* const* d_in, const int* in_sizes, int n_in,
                              void* d_out, int out_size)
{
    const float* x     = (const float*)d_in[0];
    const float* W_enc = (const float*)d_in[1];
    const float* b_enc = (const float*)d_in[2];
    const float* W_dec = (const float*)d_in[3];
    const float* b_dec = (const float*)d_in[4];

    float* out   = (float*)d_out;
    float* recon = out;                                 // [B, 768]
    float* hsp   = out + (size_t)BATCH * DIN;           // [B, 2048]
    float* hpre  = hsp + (size_t)BATCH * DHID;          // [B, 2048]

    __half *ah, *bh;
    cudaGetSymbolAddress((void**)&ah, g_Ah);
    cudaGetSymbolAddress((void**)&bh, g_Bh);

    cudaFuncSetAttribute(gemm_fp16, cudaFuncAttributeMaxDynamicSharedMemorySize,
                         (int)GEMM_SMEM);

    round_x_kernel<<<(BATCH * DIN / 2) / 256, 256>>>(x, ah);
    round_x_kernel<<<(DHID * DIN / 2) / 256, 256>>>(W_enc, bh);
    transpose_kernel<<<dim3(DHID / 32, DIN / 32), dim3(32, 8)>>>(W_dec);
    gemm_fp16<<<dim3(DHID / 128, BATCH / 128), 256, GEMM_SMEM>>>(b_enc, hpre);
    topk_kernel<<<BATCH / 8, 256>>>(hpre, hsp, x, W_enc);
    decode_kernel<<<BATCH, 192>>>(b_dec, recon);
}

// round 15
// speedup vs baseline: 1.9300x; 1.0599x over previous
#include <cuda_runtime.h>
#include <cuda_fp16.h>
#include <mma.h>
#include <cstdint>

using namespace nvcuda;

#define BATCH 32768
#define DIN   768
#define DHID  2048
#define TOPK  32

// -------- scratch (no cudaMalloc allowed) --------
__device__ __align__(16) __half g_Wt[(size_t)DHID * DIN];  // W_dec^T fp16 [2048][768]
__device__ int   g_tidx[(size_t)BATCH * TOPK];
__device__ float g_tval[(size_t)BATCH * TOPK];
__device__ __align__(16) __half g_Ah[(size_t)BATCH * DIN];  // x rounded to fp16
__device__ __align__(16) __half g_Bh[(size_t)DHID * DIN];   // W_enc rounded to fp16

// ============================================================
// f32 -> fp16 round (used for both x and W_enc)
// ============================================================
__global__ __launch_bounds__(256)
void round_x_kernel(const float* __restrict__ src, __half* __restrict__ dst)
{
    int i = blockIdx.x * 256 + threadIdx.x;
    float2 v = ((const float2*)src)[i];
    ((__half2*)dst)[i] = __floats2half2_rn(v.x, v.y);
}

// ============================================================
// W_dec [768][2048] -> g_Wt [2048][768] (fp16)
// ============================================================
__global__ void transpose_kernel(const float* __restrict__ W)
{
    __shared__ float tile[32][33];
    int bx = blockIdx.x * 32, by = blockIdx.y * 32;
    int tx = threadIdx.x, ty = threadIdx.y;
#pragma unroll
    for (int i = 0; i < 32; i += 8)
        tile[ty + i][tx] = W[(size_t)(by + ty + i) * DHID + bx + tx];
    __syncthreads();
#pragma unroll
    for (int i = 0; i < 32; i += 8)
        g_Wt[(size_t)(bx + ty + i) * DIN + by + tx] = __float2half_rn(tile[tx][ty + i]);
}

// ============================================================
// Encoder GEMM, pure fp16, cp.async 3-stage, BK=64, 2 CTAs/SM.
// Block 128x128, 8 warps (Wm=2,Wn=4), warp tile 64x32.
// Order: wait_group 1 -> sync -> issue load(t+2) -> compute(t)
// (race-free: load target buffer = compute(t-1)'s, done at sync)
// ============================================================
#define BK     64
#define HS     72                       // halves per row (64 + 8 pad, 144B)
#define PART   (128 * HS)               // 9216 halves
#define STG_H  (2 * PART)               // 18432 halves / stage
#define NKT    (DIN / BK)               // 12
#define GEMM_SMEM (3 * STG_H * sizeof(__half))   // 110592 B

__device__ __forceinline__ void cp16(__half* dst, const __half* src)
{
    unsigned d = (unsigned)__cvta_generic_to_shared(dst);
    asm volatile("cp.async.cg.shared.global [%0], [%1], 16;\n" :: "r"(d), "l"(src));
}

__global__ __launch_bounds__(256, 2)
void gemm_fp16(const float* __restrict__ bias, float* __restrict__ C)
{
    extern __shared__ __half smh[];   // 3 stages

    int tid  = threadIdx.x;
    int warp = tid >> 5;
    int wm   = warp & 1;
    int wn   = warp >> 1;
    int m0 = blockIdx.y * 128;
    int n0 = blockIdx.x * 128;

    using FragA = wmma::fragment<wmma::matrix_a, 16, 16, 16, __half, wmma::row_major>;
    using FragB = wmma::fragment<wmma::matrix_b, 16, 16, 16, __half, wmma::col_major>;
    using FragC = wmma::fragment<wmma::accumulator, 16, 16, 16, float>;

    float* bsm = (float*)smh;
    for (int i = tid; i < 16 * 128; i += 256)
        bsm[i] = bias[n0 + (i & 127)];
    __syncthreads();

    FragC acc[4][2];
#pragma unroll
    for (int i = 0; i < 4; i++)
#pragma unroll
        for (int j = 0; j < 2; j++)
            wmma::load_matrix_sync(acc[i][j], &bsm[wn * 32 + j * 16], 128, wmma::mem_row_major);
    __syncthreads();

    // per part: 128 rows x 64 halves = 1024 cp16 = 4 per thread per part
    auto load_tile = [&](int buf, int kt) {
        __half* s = smh + buf * STG_H;
        int k0 = kt * BK;
#pragma unroll
        for (int p = 0; p < 4; p++) {
            int f  = tid + p * 256;      // 0..1023
            int r  = f >> 3;             // 0..127
            int ch = (f & 7) * 8;        // halves offset 0..56
            size_t ga = (size_t)(m0 + r) * DIN + k0 + ch;
            size_t gb = (size_t)(n0 + r) * DIN + k0 + ch;
            cp16(&s[0 * PART + r * HS + ch], &g_Ah[ga]);
            cp16(&s[1 * PART + r * HS + ch], &g_Bh[gb]);
        }
        asm volatile("cp.async.commit_group;\n" ::);
    };

    // ---- prologue: 2 tiles in flight ----
    load_tile(0, 0);
    load_tile(1, 1);

    int buf = 0;
    for (int t = 0; t < NKT; t++) {
        asm volatile("cp.async.wait_group 1;\n" ::);
        __syncthreads();                 // tile t landed; compute(t-1) done

        if (t + 2 < NKT) load_tile((t + 2) % 3, t + 2);
        else             asm volatile("cp.async.commit_group;\n" ::);

        __half* s  = smh + buf * STG_H;
        buf = (buf + 1 == 3) ? 0 : buf + 1;
        __half* Ah = s;
        __half* Bh = s + PART;

#pragma unroll
        for (int ks = 0; ks < BK; ks += 16) {
            FragB bh[2];
#pragma unroll
            for (int j = 0; j < 2; j++)
                wmma::load_matrix_sync(bh[j], &Bh[(wn * 32 + j * 16) * HS + ks], HS);
#pragma unroll
            for (int i = 0; i < 4; i++) {
                FragA ah;
                wmma::load_matrix_sync(ah, &Ah[(wm * 64 + i * 16) * HS + ks], HS);
#pragma unroll
                for (int j = 0; j < 2; j++)
                    wmma::mma_sync(acc[i][j], ah, bh[j], acc[i][j]);
            }
        }
    }

#pragma unroll
    for (int i = 0; i < 4; i++)
#pragma unroll
        for (int j = 0; j < 2; j++) {
            float* cp = &C[(size_t)(m0 + wm * 64 + i * 16) * DHID + n0 + wn * 32 + j * 16];
            wmma::store_matrix_sync(cp, acc[i][j], DHID, wmma::mem_row_major);
        }
}

// ============================================================
// Top-K v3.1: candidate-compressed bisection (ballot counting)
// + exact fp64 re-rank of the ambiguous boundary.
// Element layout: val[4g+c] = column g*128 + lane*4 + c.
// ============================================================
#define AMBIG_W 1.5e-3f
#define MAXCAND 16

__device__ __forceinline__ unsigned fmono(float f)
{
    unsigned u = __float_as_uint(f);
    return (u & 0x80000000u) ? ~u : (u | 0x80000000u);
}
__device__ __forceinline__ float key_decode(unsigned k)
{
    return (k >= 0x80000000u) ? __uint_as_float(k ^ 0x80000000u)
                              : __uint_as_float(~k);
}

__global__ __launch_bounds__(256, 2)
void topk_kernel(const float* __restrict__ hpre, float* __restrict__ hsp,
                 const float* __restrict__ x, const float* __restrict__ Wenc)
{
    const unsigned FULL = 0xFFFFFFFFu;
    int lane = threadIdx.x & 31;
    int warp = threadIdx.x >> 5;
    int row  = blockIdx.x * 8 + warp;
    const float4* p4 = (const float4*)(hpre + (size_t)row * DHID);
    unsigned lmask = (1u << lane) - 1u;

    __shared__ float  s_cv[8][128];
    __shared__ int    s_cidx[8][MAXCAND];
    __shared__ double s_cval[8][MAXCAND];
    __shared__ int    s_csel[8][MAXCAND];
    __shared__ unsigned s_chosen[8];

    float val[64];
    float vmax = -3.0e38f;
#pragma unroll
    for (int g = 0; g < 16; g++) {
        float4 v = p4[g * 32 + lane];
        val[4*g+0] = v.x; val[4*g+1] = v.y; val[4*g+2] = v.z; val[4*g+3] = v.w;
        vmax = fmaxf(vmax, fmaxf(fmaxf(v.x, v.y), fmaxf(v.z, v.w)));
    }

    unsigned lo = __reduce_min_sync(FULL, fmono(vmax));
    unsigned hi = __reduce_max_sync(FULL, fmono(vmax));
    float loF = key_decode(lo);

    int c_lo;
    {
        int c = 0;
#pragma unroll
        for (int j = 0; j < 64; j++) c += (val[j] >= loF) ? 1 : 0;
        c_lo = __reduce_add_sync(FULL, c);
    }
#pragma unroll 1
    for (int it = 0; it < 32 && c_lo > 128 && lo < hi; ++it) {
        unsigned span = hi - lo;
        unsigned mid = lo + (span >> 1) + (span & 1u);
        float mf = key_decode(mid);
        int c = 0;
#pragma unroll
        for (int j = 0; j < 64; j++) c += (val[j] >= mf) ? 1 : 0;
        c = __reduce_add_sync(FULL, c);
        if (c >= TOPK) { lo = mid; loF = mf; c_lo = c; }
        else            hi = mid - 1;
    }

    int cnt = 0;
#pragma unroll
    for (int j = 0; j < 64; j++) cnt += (val[j] >= loF) ? 1 : 0;
    int off = cnt;
#pragma unroll
    for (int d = 1; d < 32; d <<= 1) {
        int n = __shfl_up_sync(FULL, off, d);
        if (lane >= d) off += n;
    }
    int ncand = __shfl_sync(FULL, off, 31);
    off -= cnt;
    {
        int o = off;
#pragma unroll
        for (int j = 0; j < 64; j++) {
            if (val[j] >= loF) {
                if (o < 128) s_cv[warp][o] = val[j];
                o++;
            }
        }
    }
    if (ncand > 128) ncand = 128;
    __syncwarp();

    float cv[4];
#pragma unroll
    for (int r = 0; r < 4; r++) {
        int pos = lane + r * 32;
        cv[r] = (pos < ncand) ? s_cv[warp][pos] : -3.0e38f;
    }

    // ---- fine bisection, ballot-popc counting (uniform result) ----
#pragma unroll 1
    for (int it = 0; it < 32; ++it) {
        if (lo >= hi) break;
        unsigned span = hi - lo;
        unsigned mid = lo + (span >> 1) + (span & 1u);
        float mf = key_decode(mid);
        int c = 0;
#pragma unroll
        for (int r = 0; r < 4; r++)
            c += __popc(__ballot_sync(FULL, cv[r] >= mf));
        if (c >= TOPK) lo = mid; else hi = mid - 1;
    }
    float Tf = key_decode(lo);

    int cg = 0;
#pragma unroll
    for (int r = 0; r < 4; r++)
        cg += __popc(__ballot_sync(FULL, cv[r] > Tf));
    int rem = TOPK - cg;

    unsigned long long selmask = 0ull, tiemask = 0ull;
    float vin_l = 3.0e38f, vout_l = -3.0e38f;
#pragma unroll
    for (int j = 0; j < 64; j++) {
        float v = val[j];
        if (v > Tf)       { selmask |= 1ull << j; vin_l = fminf(vin_l, v); }
        else if (v == Tf) { tiemask |= 1ull << j; }
        else              { vout_l = fmaxf(vout_l, v); }
    }
    int tcnt = __popcll(tiemask);
    int toff = tcnt;
#pragma unroll
    for (int d = 1; d < 32; d <<= 1) {
        int n = __shfl_up_sync(FULL, toff, d);
        if (lane >= d) toff += n;
    }
    toff -= tcnt;
    {
        int r = toff;
#pragma unroll
        for (int j = 0; j < 64; j++) {
            if ((tiemask >> j) & 1ull) {
                if (r < rem) { selmask |= 1ull << j; vin_l = fminf(vin_l, val[j]); }
                else         { vout_l = fmaxf(vout_l, val[j]); }
                r++;
            }
        }
    }

    unsigned vi = __reduce_min_sync(FULL, fmono(vin_l));
    unsigned vo = __reduce_max_sync(FULL, fmono(vout_l));
    float vin  = key_decode(vi);
    float vout = key_decode(vo);

    if (vin - vout < AMBIG_W) {
        float wlo = vout - AMBIG_W;
        float whi = vin + AMBIG_W;
        int ncw = 0;
#pragma unroll 1
        for (int j = 0; j < 64; j++) {
            float v = val[j];
            bool isc = (v >= wlo) && (v <= whi);
            unsigned bal = __ballot_sync(FULL, isc);
            if (isc) {
                int pos = ncw + __popc(bal & lmask);
                if (pos < MAXCAND) {
                    s_cidx[warp][pos] = (j >> 2) * 128 + lane * 4 + (j & 3);
                    s_csel[warp][pos] = (int)((selmask >> j) & 1ull);
                }
            }
            ncw += __popc(bal);
        }
        if (ncw > MAXCAND) ncw = MAXCAND;
        __syncwarp();

        const float* xr = x + (size_t)row * DIN;
        for (int c = 0; c < ncw; c++) {
            const float* wr = Wenc + (size_t)s_cidx[warp][c] * DIN;
            double s = 0.0;
#pragma unroll
            for (int t = 0; t < DIN / 32; t++) {
                int kk = lane + t * 32;
                s += (double)xr[kk] * (double)wr[kk];
            }
#pragma unroll
            for (int o2 = 16; o2 > 0; o2 >>= 1)
                s += __shfl_down_sync(FULL, s, o2);
            if (lane == 0) s_cval[warp][c] = s;
            __syncwarp();
        }

        if (lane == 0) {
            int nkeep = 0;
            for (int c = 0; c < ncw; c++) nkeep += s_csel[warp][c];
            unsigned chosen = 0;
            for (int s = 0; s < nkeep; s++) {
                int best = -1;
                for (int c = 0; c < ncw; c++) {
                    if (chosen & (1u << c)) continue;
                    if (best < 0 ||
                        s_cval[warp][c] > s_cval[warp][best] ||
                        (s_cval[warp][c] == s_cval[warp][best] &&
                         s_cidx[warp][c] < s_cidx[warp][best]))
                        best = c;
                }
                chosen |= (1u << best);
            }
            s_chosen[warp] = chosen;
        }
        __syncwarp();
        unsigned chosen = s_chosen[warp];

        for (int c = 0; c < ncw; c++) {
            int fi = s_cidx[warp][c];
            if (((fi >> 2) & 31) == lane) {
                int j = ((fi >> 7) << 2) | (fi & 3);
                if (chosen & (1u << c)) selmask |=  (1ull << j);
                else                    selmask &= ~(1ull << j);
            }
        }
        __syncwarp();
    }

    float4* orow4 = (float4*)(hsp + (size_t)row * DHID);
#pragma unroll
    for (int g = 0; g < 16; g++) {
        float4 o;
        o.x = ((selmask >> (4*g+0)) & 1ull) ? fmaxf(val[4*g+0], 0.0f) : 0.0f;
        o.y = ((selmask >> (4*g+1)) & 1ull) ? fmaxf(val[4*g+1], 0.0f) : 0.0f;
        o.z = ((selmask >> (4*g+2)) & 1ull) ? fmaxf(val[4*g+2], 0.0f) : 0.0f;
        o.w = ((selmask >> (4*g+3)) & 1ull) ? fmaxf(val[4*g+3], 0.0f) : 0.0f;
        orow4[g * 32 + lane] = o;
    }

    int scnt = __popcll(selmask);
    int soff = scnt;
#pragma unroll
    for (int d = 1; d < 32; d <<= 1) {
        int n = __shfl_up_sync(FULL, soff, d);
        if (lane >= d) soff += n;
    }
    int nsel_tot = __shfl_sync(FULL, soff, 31);
    soff -= scnt;
    {
        int so = soff;
#pragma unroll
        for (int j = 0; j < 64; j++) {
            if ((selmask >> j) & 1ull) {
                if (so < TOPK) {
                    g_tidx[(size_t)row * TOPK + so] = (j >> 2) * 128 + lane * 4 + (j & 3);
                    g_tval[(size_t)row * TOPK + so] = fmaxf(val[j], 0.0f);
                }
                so++;
            }
        }
    }
    if (nsel_tot < TOPK && lane == 0) {
        for (int s = nsel_tot; s < TOPK; s++) {
            g_tidx[(size_t)row * TOPK + s] = 0;
            g_tval[(size_t)row * TOPK + s] = 0.0f;
        }
    }
}

// ============================================================
// Sparse decoder: recon[row,:] = b_dec + sum_k val_k * Wt[idx_k,:]
// Wt in fp16 (math fp32); traffic halved vs fp32 Wt.
// ============================================================
__global__ __launch_bounds__(192)
void decode_kernel(const float* __restrict__ bdec, float* __restrict__ recon)
{
    int row = blockIdx.x;
    int t = threadIdx.x;
    __shared__ float sval[TOPK];
    __shared__ int   sidx[TOPK];
    if (t < TOPK) {
        sval[t] = g_tval[(size_t)row * TOPK + t];
        sidx[t] = g_tidx[(size_t)row * TOPK + t];
    }
    __syncthreads();

    float4 acc = *(const float4*)&bdec[t * 4];
#pragma unroll 8
    for (int k = 0; k < TOPK; k++) {
        float v = sval[k];
        const __half* wr = g_Wt + (size_t)sidx[k] * DIN;
        uint2 u = ((const uint2*)wr)[t];
        __half2 h01 = *(__half2*)&u.x;
        __half2 h23 = *(__half2*)&u.y;
        float2 f01 = __half22float2(h01);
        float2 f23 = __half22float2(h23);
        acc.x += v * f01.x; acc.y += v * f01.y;
        acc.z += v * f23.x; acc.w += v * f23.y;
    }
    *(float4*)&recon[(size_t)row * DIN + t * 4] = acc;
}

// ============================================================
extern "C" void kernel_launch(void* const* d_in, const int* in_sizes, int n_in,
                              void* d_out, int out_size)
{
    const float* x     = (const float*)d_in[0];
    const float* W_enc = (const float*)d_in[1];
    const float* b_enc = (const float*)d_in[2];
    const float* W_dec = (const float*)d_in[3];
    const float* b_dec = (const float*)d_in[4];

    float* out   = (float*)d_out;
    float* recon = out;                                 // [B, 768]
    float* hsp   = out + (size_t)BATCH * DIN;           // [B, 2048]
    float* hpre  = hsp + (size_t)BATCH * DHID;          // [B, 2048]

    __half *ah, *bh;
    cudaGetSymbolAddress((void**)&ah, g_Ah);
    cudaGetSymbolAddress((void**)&bh, g_Bh);

    cudaFuncSetAttribute(gemm_fp16, cudaFuncAttributeMaxDynamicSharedMemorySize,
                         (int)GEMM_SMEM);

    round_x_kernel<<<(BATCH * DIN / 2) / 256, 256>>>(x, ah);
    round_x_kernel<<<(DHID * DIN / 2) / 256, 256>>>(W_enc, bh);
    transpose_kernel<<<dim3(DHID / 32, DIN / 32), dim3(32, 8)>>>(W_dec);
    gemm_fp16<<<dim3(DHID / 128, BATCH / 128), 256, GEMM_SMEM>>>(b_enc, hpre);
    topk_kernel<<<BATCH / 8, 256>>>(hpre, hsp, x, W_enc);
    decode_kernel<<<BATCH, 192>>>(b_dec, recon);
}